// round 1
// baseline (speedup 1.0000x reference)
#include <cuda_runtime.h>

// TFLoudnessLoss: multi-band (8) loudness difference with softmax weighting.
// Pipeline: forward FFT(160000 = 256x625) per signal (16 signals),
// per-band masked inverse FFT, hop-block energies, loudness diffs, softmax.
//
// Four-step FFT:  n = n1 + 256*n2,  k = k2 + 625*k1
//   Fwd:  A[n1,k2] = FFT625_{n2}(x[n1+256 n2]);  B = A * W_L^{n1 k2};
//         X[k2+625 k1] = FFT256_{n1}(B[n1,k2])
//   Inv:  C[k2,n1] = IFFT256_{k1}(mask_b * X[k2+625 k1]);  D = C * conj(W_L^{k2 n1});
//         y[n1+256 n2] = (1/L) IFFT625_{k2}(D[k2,n1])
// Energies: block j (1024 samples) gets n2 in [4j,4j+4) for each n1.

#define LTOT 160000
#define NSIG 16
#define NBLK 156
#define NCH  155
#define NDIFF (8*8*155)

__device__ float2 d_W[LTOT];            // e^{-2*pi*i*m/L}
__device__ float2 d_spec[NSIG*LTOT];    // X: [s][k2*256 + k1]
__device__ float2 d_work[NSIG*LTOT];    // fwd intermediate B / inv intermediate C [s][n1*625+k2]
__device__ float  d_P[NSIG*NBLK*256];   // partial block energies [s][j][n1]
__device__ float  d_blk[NSIG*NBLK];     // block energies
__device__ float  d_diff[NDIFF];        // loudness diffs

__device__ __forceinline__ float2 cmulf(float2 a, float2 b){
  return make_float2(fmaf(a.x,b.x,-a.y*b.y), fmaf(a.x,b.y,a.y*b.x));
}
__device__ __forceinline__ float2 cadd(float2 a,float2 b){return make_float2(a.x+b.x,a.y+b.y);}
__device__ __forceinline__ float2 csub(float2 a,float2 b){return make_float2(a.x-b.x,a.y-b.y);}

__global__ void k_genW(){
  int m = blockIdx.x*blockDim.x + threadIdx.x;
  if (m < LTOT){
    float t = (float)((double)m / 80000.0);   // 2m/L in [0,2)
    float s, c;
    sincospif(t, &s, &c);
    d_W[m] = make_float2(c, -s);
  }
}

template<int SIGN>
__device__ __forceinline__ void dft5(float2 v[5]){
  const float C1 = 0.30901699437494745f;
  const float S1 = 0.95105651629515353f;
  const float C2 = -0.80901699437494745f;
  const float S2 = 0.58778525229247314f;
  float2 w1 = make_float2(C1,  SIGN*S1);
  float2 w2 = make_float2(C2,  SIGN*S2);
  float2 w3 = make_float2(C2, -SIGN*S2);
  float2 w4 = make_float2(C1, -SIGN*S1);
  float2 o0 = cadd(cadd(v[0],v[1]), cadd(cadd(v[2],v[3]),v[4]));
  float2 o1 = cadd(v[0], cadd(cadd(cmulf(v[1],w1),cmulf(v[2],w2)), cadd(cmulf(v[3],w3),cmulf(v[4],w4))));
  float2 o2 = cadd(v[0], cadd(cadd(cmulf(v[1],w2),cmulf(v[2],w4)), cadd(cmulf(v[3],w1),cmulf(v[4],w3))));
  float2 o3 = cadd(v[0], cadd(cadd(cmulf(v[1],w3),cmulf(v[2],w1)), cadd(cmulf(v[3],w4),cmulf(v[4],w2))));
  float2 o4 = cadd(v[0], cadd(cadd(cmulf(v[1],w4),cmulf(v[2],w3)), cadd(cmulf(v[3],w2),cmulf(v[4],w1))));
  v[0]=o0; v[1]=o1; v[2]=o2; v[3]=o3; v[4]=o4;
}

template<int SIGN>
__device__ __forceinline__ void dft4(float2 v[4]){
  float2 s02 = cadd(v[0],v[2]), d02 = csub(v[0],v[2]);
  float2 s13 = cadd(v[1],v[3]), d13 = csub(v[1],v[3]);
  float2 id13 = make_float2(-d13.y, d13.x);
  float2 o0 = cadd(s02, s13);
  float2 o2 = csub(s02, s13);
  float2 o1, o3;
  if (SIGN < 0){ o1 = csub(d02, id13); o3 = cadd(d02, id13); }
  else         { o1 = cadd(d02, id13); o3 = csub(d02, id13); }
  v[0]=o0; v[1]=o1; v[2]=o2; v[3]=o3;
}

// Stockham radix-5, N=625, lanes 0..124 active (call with lane in [0,128)). Result in A.
template<int SIGN>
__device__ void fft625(float2* __restrict__ A, float2* __restrict__ B, int lane){
  float2* src = A; float2* dst = B;
  int Ns = 1;
  #pragma unroll
  for (int t=0;t<4;t++){
    if (lane < 125){
      int j = lane;
      int jNs = j % Ns;                 // Ns is compile-time per unrolled iter
      int f = LTOT/(Ns*5);
      float2 v[5];
      #pragma unroll
      for (int r=0;r<5;r++){
        float2 x = src[j + r*125];
        int m = r*jNs*f;
        if (m){
          float2 w = d_W[m];
          if (SIGN>0) w.y = -w.y;
          x = cmulf(x,w);
        }
        v[r]=x;
      }
      dft5<SIGN>(v);
      int idxD = (j/Ns)*(Ns*5) + jNs;
      #pragma unroll
      for (int r=0;r<5;r++) dst[idxD + r*Ns] = v[r];
    }
    __syncthreads();
    float2* tmp = src; src = dst; dst = tmp;
    Ns *= 5;
  }
}

// Stockham radix-4, N=256, lanes 0..63 (all active). Result in A.
template<int SIGN>
__device__ void fft256(float2* __restrict__ A, float2* __restrict__ B, int lane){
  float2* src = A; float2* dst = B;
  int Ns = 1;
  #pragma unroll
  for (int t=0;t<4;t++){
    {
      int j = lane;
      int jNs = j % Ns;
      int f = LTOT/(Ns*4);
      float2 v[4];
      #pragma unroll
      for (int r=0;r<4;r++){
        float2 x = src[j + r*64];
        int m = r*jNs*f;
        if (m){
          float2 w = d_W[m];
          if (SIGN>0) w.y = -w.y;
          x = cmulf(x,w);
        }
        v[r]=x;
      }
      dft4<SIGN>(v);
      int idxD = (j/Ns)*(Ns*4) + jNs;
      #pragma unroll
      for (int r=0;r<4;r++) dst[idxD + r*Ns] = v[r];
    }
    __syncthreads();
    float2* tmp = src; src = dst; dst = tmp;
    Ns *= 4;
  }
}

// Forward stage 1: per (signal, n1): FFT625 over n2, twiddle, write B[s][k2*256+n1]
__global__ void __launch_bounds__(512) k_fwd1(const float* __restrict__ xw, const float* __restrict__ xo){
  __shared__ float2 sh[4][2][625];
  int tid = threadIdx.x;
  int sub = tid >> 7, lane = tid & 127;
  int n1b = blockIdx.x*4;
  int s   = blockIdx.y;
  const float* x = (s < 8) ? (xw + s*LTOT) : (xo + (s-8)*LTOT);
  for (int w = tid; w < 2500; w += 512){
    int n2 = w >> 2, sb = w & 3;
    sh[sb][0][n2] = make_float2(x[n1b + sb + 256*n2], 0.f);
  }
  __syncthreads();
  fft625<-1>(sh[sub][0], sh[sub][1], lane);
  float2* out = d_work + s*LTOT;
  for (int w = tid; w < 2500; w += 512){
    int k2 = w >> 2, sb = w & 3;
    int n1 = n1b + sb;
    float2 v = cmulf(sh[sb][0][k2], d_W[n1*k2]);
    out[k2*256 + n1] = v;
  }
}

// Forward stage 2: per (signal, k2): FFT256 over n1 -> X[s][k2*256+k1]
__global__ void __launch_bounds__(256) k_fwd2(){
  __shared__ float2 sh[4][2][256];
  int tid = threadIdx.x, sub = tid>>6, lane = tid&63;
  int row = blockIdx.x*4 + sub;            // 0..9999 = s*625 + k2
  int s = row / 625, k2 = row - s*625;
  const float2* in = d_work + s*LTOT + k2*256;
  for (int i = lane; i < 256; i += 64) sh[sub][0][i] = in[i];
  __syncthreads();
  fft256<-1>(sh[sub][0], sh[sub][1], lane);
  float2* out = d_spec + s*LTOT + k2*256;
  for (int i = lane; i < 256; i += 64) out[i] = sh[sub][0][i];
}

__device__ __forceinline__ int band_of(int k){
  if (k == 0) return 7;
  int f = (k < LTOT - k) ? k : (LTOT - k);
  return (f - 1) / 10000;
}

// Inverse stage 1 (per band): mask + IFFT256 over k1, twiddle, write C[s][n1*625+k2]
__global__ void __launch_bounds__(256) k_inv1(int b){
  __shared__ float2 sh[4][2][256];
  int tid = threadIdx.x, sub = tid>>6, lane = tid&63;
  int row = blockIdx.x*4 + sub;
  int s = row / 625, k2 = row - s*625;
  const float2* in = d_spec + s*LTOT + k2*256;
  for (int k1 = lane; k1 < 256; k1 += 64){
    int k = k2 + 625*k1;
    float2 v = (band_of(k) == b) ? in[k1] : make_float2(0.f, 0.f);
    sh[sub][0][k1] = v;
  }
  __syncthreads();
  fft256<1>(sh[sub][0], sh[sub][1], lane);
  for (int w = tid; w < 1024; w += 256){
    int n1 = w >> 2, sb = w & 3;
    int row2 = blockIdx.x*4 + sb;
    int s2 = row2 / 625, k22 = row2 - s2*625;
    float2 tw = d_W[k22*n1];
    tw.y = -tw.y;                          // conj -> e^{+2pi i k2 n1 / L}
    d_work[s2*LTOT + n1*625 + k22] = cmulf(sh[sb][0][n1], tw);
  }
}

// Inverse stage 2: IFFT625 over k2 -> y at n = n1+256*n2; partial block energies
__global__ void __launch_bounds__(512) k_inv2(){
  __shared__ float2 sh[4][2][625];
  int tid = threadIdx.x, sub = tid>>7, lane = tid&127;
  int n1b = blockIdx.x*4, s = blockIdx.y;
  const float2* in = d_work + s*LTOT + (n1b+sub)*625;
  for (int i = lane; i < 625; i += 128) sh[sub][0][i] = in[i];
  __syncthreads();
  fft625<1>(sh[sub][0], sh[sub][1], lane);
  float* scratch = (float*)&sh[sub][1][0];   // buffer B is free now
  const float invL = 1.0f/160000.0f;
  for (int j = lane; j < NBLK; j += 128){
    float p = 0.f;
    #pragma unroll
    for (int q=0;q<4;q++){
      float y = sh[sub][0][4*j+q].x * invL;
      p = fmaf(y, y, p);
    }
    scratch[j] = p;
  }
  __syncthreads();
  for (int w = tid; w < NBLK*4; w += 512){
    int j = w >> 2, sb = w & 3;
    float* sc = (float*)&sh[sb][1][0];
    d_P[(s*NBLK + j)*256 + n1b + sb] = sc[j];
  }
}

// Reduce partials over n1 (fixed order -> deterministic)
__global__ void k_red(){
  int idx = blockIdx.x*blockDim.x + threadIdx.x;
  if (idx < NSIG*NBLK){
    const float4* p = (const float4*)(d_P + idx*256);
    float sum = 0.f;
    #pragma unroll 8
    for (int i=0;i<64;i++){
      float4 v = p[i];
      sum += (v.x + v.y) + (v.z + v.w);
    }
    d_blk[idx] = sum;
  }
}

// Loudness diffs for band b
__global__ void k_diff(int b){
  int t = blockIdx.x*blockDim.x + threadIdx.x;
  if (t < 8*NCH){
    int s = t / NCH, j = t - s*NCH;
    float ew = d_blk[s*NBLK + j]     + d_blk[s*NBLK + j + 1];
    float eo = d_blk[(s+8)*NBLK + j] + d_blk[(s+8)*NBLK + j + 1];
    float lw = 10.f*log10f(ew*(1.f/2048.f) + 1e-12f);
    float lo = 10.f*log10f(eo*(1.f/2048.f) + 1e-12f);
    d_diff[(s*8 + b)*NCH + j] = lw - lo;    // -0.691 cancels in the diff
  }
}

// softmax(diff) . diff  (deterministic tree reductions)
__global__ void __launch_bounds__(1024) k_final(float* __restrict__ out){
  __shared__ float smax[1024];
  __shared__ float ssum[1024];
  __shared__ float swt[1024];
  int tid = threadIdx.x;
  float m = -1e30f;
  for (int i = tid; i < NDIFF; i += 1024) m = fmaxf(m, d_diff[i]);
  smax[tid] = m; __syncthreads();
  for (int st = 512; st > 0; st >>= 1){
    if (tid < st) smax[tid] = fmaxf(smax[tid], smax[tid+st]);
    __syncthreads();
  }
  float mx = smax[0];
  float se = 0.f, sw = 0.f;
  for (int i = tid; i < NDIFF; i += 1024){
    float d = d_diff[i];
    float e = expf(d - mx);
    se += e;
    sw = fmaf(e, d, sw);
  }
  ssum[tid] = se; swt[tid] = sw; __syncthreads();
  for (int st = 512; st > 0; st >>= 1){
    if (tid < st){ ssum[tid] += ssum[tid+st]; swt[tid] += swt[tid+st]; }
    __syncthreads();
  }
  if (tid == 0) out[0] = swt[0] / ssum[0];
}

extern "C" void kernel_launch(void* const* d_in, const int* in_sizes, int n_in,
                              void* d_out, int out_size){
  const float* xw = (const float*)d_in[0];   // watermarked_signals [8,160000]
  const float* xo = (const float*)d_in[1];   // original_signals    [8,160000]
  float* out = (float*)d_out;

  k_genW<<<(LTOT+255)/256, 256>>>();
  k_fwd1<<<dim3(64,16), 512>>>(xw, xo);
  k_fwd2<<<2500, 256>>>();
  for (int b = 0; b < 8; b++){
    k_inv1<<<2500, 256>>>(b);
    k_inv2<<<dim3(64,16), 512>>>();
    k_red<<<10, 256>>>();
    k_diff<<<5, 256>>>(b);
  }
  k_final<<<1, 1024>>>(out);
}

// round 2
// speedup vs baseline: 1.5817x; 1.5817x over previous
#include <cuda_runtime.h>

// TFLoudnessLoss: multi-band (8) loudness difference with softmax weighting.
// Four-step FFT:  n = n1 + 256*n2,  k = k2 + 625*k1   (L = 160000 = 256*625)
//   Fwd:  A[n1,k2] = FFT625_{n2}(x[n1+256 n2]);  B = A * W_L^{n1 k2};
//         X[k2+625 k1] = FFT256_{n1}(B[n1,k2])
//   Inv (per band): C[k2,n1] = IFFT256_{k1}(mask_b * X);  D = C * conj(W_L^{k2 n1});
//         y[n1+256 n2] = (1/L) IFFT625_{k2}(D[k2,n1])
// Band structure: with k1 = j + 16 r (j,r in [0,16)), for k2>=1 the band of
// k = k2+625*k1 is  band(r) = r<8 ? r : 15-r  -- independent of j.

#define LTOT 160000
#define NSIG 16
#define NBLK 156
#define NCH  155
#define NDIFF (8*8*155)
#define NBS 128            /* 8 bands x 16 signals */

__device__ float2 d_W[LTOT];              // e^{-2*pi*i*m/L}
__device__ float2 d_W16[16];              // e^{-2*pi*i*m/16}
__device__ float2 d_W25[25];              // e^{-2*pi*i*m/25}
__device__ float2 d_spec[NSIG*LTOT];      // X: [s][k2*256 + k1]
__device__ float2 d_work[NSIG*LTOT];      // fwd intermediate [s][k2*256+n1]
__device__ float2 d_work8[(size_t)NBS*LTOT];  // inv intermediate [b*16+s][n1*625+k2]
__device__ float  d_P[NBS*NBLK*256];      // partial block energies [bs][j][n1]
__device__ float  d_blk[NBS*NBLK];        // block energies
__device__ float  d_diff[NDIFF];          // loudness diffs

__device__ __forceinline__ float2 cmulf(float2 a, float2 b){
  return make_float2(fmaf(a.x,b.x,-a.y*b.y), fmaf(a.x,b.y,a.y*b.x));
}
__device__ __forceinline__ float2 cadd(float2 a,float2 b){return make_float2(a.x+b.x,a.y+b.y);}
__device__ __forceinline__ float2 csub(float2 a,float2 b){return make_float2(a.x-b.x,a.y-b.y);}

__global__ void k_genW(){
  int m = blockIdx.x*blockDim.x + threadIdx.x;
  if (m < LTOT){
    float t = (float)((double)m / 80000.0);   // 2m/L
    float s, c;
    sincospif(t, &s, &c);
    d_W[m] = make_float2(c, -s);
  }
  if (blockIdx.x == 0 && threadIdx.x < 25){
    int q = threadIdx.x;
    if (q < 16){
      float s, c; sincospif(2.f*q/16.f, &s, &c);
      d_W16[q] = make_float2(c, -s);
    }
    float s, c; sincospif(2.f*q/25.f, &s, &c);
    d_W25[q] = make_float2(c, -s);
  }
}

template<int SIGN>
__device__ __forceinline__ void dft5(float2 v[5]){
  const float C1 = 0.30901699437494745f;
  const float S1 = 0.95105651629515353f;
  const float C2 = -0.80901699437494745f;
  const float S2 = 0.58778525229247314f;
  float2 w1 = make_float2(C1,  SIGN*S1);
  float2 w2 = make_float2(C2,  SIGN*S2);
  float2 w3 = make_float2(C2, -SIGN*S2);
  float2 w4 = make_float2(C1, -SIGN*S1);
  float2 o0 = cadd(cadd(v[0],v[1]), cadd(cadd(v[2],v[3]),v[4]));
  float2 o1 = cadd(v[0], cadd(cadd(cmulf(v[1],w1),cmulf(v[2],w2)), cadd(cmulf(v[3],w3),cmulf(v[4],w4))));
  float2 o2 = cadd(v[0], cadd(cadd(cmulf(v[1],w2),cmulf(v[2],w4)), cadd(cmulf(v[3],w1),cmulf(v[4],w3))));
  float2 o3 = cadd(v[0], cadd(cadd(cmulf(v[1],w3),cmulf(v[2],w1)), cadd(cmulf(v[3],w4),cmulf(v[4],w2))));
  float2 o4 = cadd(v[0], cadd(cadd(cmulf(v[1],w4),cmulf(v[2],w3)), cadd(cmulf(v[3],w2),cmulf(v[4],w1))));
  v[0]=o0; v[1]=o1; v[2]=o2; v[3]=o3; v[4]=o4;
}

template<int SIGN>
__device__ __forceinline__ void dft4(float2 v[4]){
  float2 s02 = cadd(v[0],v[2]), d02 = csub(v[0],v[2]);
  float2 s13 = cadd(v[1],v[3]), d13 = csub(v[1],v[3]);
  float2 id13 = make_float2(-d13.y, d13.x);
  float2 o0 = cadd(s02, s13);
  float2 o2 = csub(s02, s13);
  float2 o1, o3;
  if (SIGN < 0){ o1 = csub(d02, id13); o3 = cadd(d02, id13); }
  else         { o1 = cadd(d02, id13); o3 = csub(d02, id13); }
  v[0]=o0; v[1]=o1; v[2]=o2; v[3]=o3;
}

template<int SIGN>
__device__ __forceinline__ float2 wm16(int m){
  float2 w = d_W16[m & 15];
  if (SIGN > 0) w.y = -w.y;
  return w;
}

// Full DFT16 in registers (4x4 Cooley-Tukey)
template<int SIGN>
__device__ __forceinline__ void dft16(float2 v[16]){
  float2 t[16];
  #pragma unroll
  for (int r0=0;r0<4;r0++){
    float2 a[4] = {v[r0], v[r0+4], v[r0+8], v[r0+12]};
    dft4<SIGN>(a);
    #pragma unroll
    for (int k0=0;k0<4;k0++)
      t[r0*4+k0] = (r0*k0) ? cmulf(a[k0], wm16<SIGN>(r0*k0)) : a[k0];
  }
  #pragma unroll
  for (int k0=0;k0<4;k0++){
    float2 b[4] = {t[k0], t[4+k0], t[8+k0], t[12+k0]};
    dft4<SIGN>(b);
    #pragma unroll
    for (int k1=0;k1<4;k1++) v[k0 + 4*k1] = b[k1];
  }
}

template<int SIGN>
__device__ __forceinline__ float2 wm25(int m){
  float2 w = d_W25[m];        // m <= 16
  if (SIGN > 0) w.y = -w.y;
  return w;
}

// Full DFT25 in registers (5x5 Cooley-Tukey)
template<int SIGN>
__device__ __forceinline__ void dft25(float2 v[25]){
  float2 t[25];
  #pragma unroll
  for (int r0=0;r0<5;r0++){
    float2 a[5] = {v[r0], v[r0+5], v[r0+10], v[r0+15], v[r0+20]};
    dft5<SIGN>(a);
    #pragma unroll
    for (int k0=0;k0<5;k0++)
      t[r0*5+k0] = (r0*k0) ? cmulf(a[k0], wm25<SIGN>(r0*k0)) : a[k0];
  }
  #pragma unroll
  for (int k0=0;k0<5;k0++){
    float2 b[5] = {t[k0], t[5+k0], t[10+k0], t[15+k0], t[20+k0]};
    dft5<SIGN>(b);
    #pragma unroll
    for (int k1=0;k1<5;k1++) v[k0+5*k1] = b[k1];
  }
}

// ---------------- forward path (unchanged, verified) ----------------

template<int SIGN>
__device__ void fft625(float2* __restrict__ A, float2* __restrict__ B, int lane){
  float2* src = A; float2* dst = B;
  int Ns = 1;
  #pragma unroll
  for (int t=0;t<4;t++){
    if (lane < 125){
      int j = lane;
      int jNs = j % Ns;
      int f = LTOT/(Ns*5);
      float2 v[5];
      #pragma unroll
      for (int r=0;r<5;r++){
        float2 x = src[j + r*125];
        int m = r*jNs*f;
        if (m){
          float2 w = d_W[m];
          if (SIGN>0) w.y = -w.y;
          x = cmulf(x,w);
        }
        v[r]=x;
      }
      dft5<SIGN>(v);
      int idxD = (j/Ns)*(Ns*5) + jNs;
      #pragma unroll
      for (int r=0;r<5;r++) dst[idxD + r*Ns] = v[r];
    }
    __syncthreads();
    float2* tmp = src; src = dst; dst = tmp;
    Ns *= 5;
  }
}

template<int SIGN>
__device__ void fft256s(float2* __restrict__ A, float2* __restrict__ B, int lane){
  float2* src = A; float2* dst = B;
  int Ns = 1;
  #pragma unroll
  for (int t=0;t<4;t++){
    {
      int j = lane;
      int jNs = j % Ns;
      int f = LTOT/(Ns*4);
      float2 v[4];
      #pragma unroll
      for (int r=0;r<4;r++){
        float2 x = src[j + r*64];
        int m = r*jNs*f;
        if (m){
          float2 w = d_W[m];
          if (SIGN>0) w.y = -w.y;
          x = cmulf(x,w);
        }
        v[r]=x;
      }
      dft4<SIGN>(v);
      int idxD = (j/Ns)*(Ns*4) + jNs;
      #pragma unroll
      for (int r=0;r<4;r++) dst[idxD + r*Ns] = v[r];
    }
    __syncthreads();
    float2* tmp = src; src = dst; dst = tmp;
    Ns *= 4;
  }
}

__global__ void __launch_bounds__(512) k_fwd1(const float* __restrict__ xw, const float* __restrict__ xo){
  __shared__ float2 sh[4][2][625];
  int tid = threadIdx.x;
  int sub = tid >> 7, lane = tid & 127;
  int n1b = blockIdx.x*4;
  int s   = blockIdx.y;
  const float* x = (s < 8) ? (xw + s*LTOT) : (xo + (s-8)*LTOT);
  for (int w = tid; w < 2500; w += 512){
    int n2 = w >> 2, sb = w & 3;
    sh[sb][0][n2] = make_float2(x[n1b + sb + 256*n2], 0.f);
  }
  __syncthreads();
  fft625<-1>(sh[sub][0], sh[sub][1], lane);
  float2* out = d_work + s*LTOT;
  for (int w = tid; w < 2500; w += 512){
    int k2 = w >> 2, sb = w & 3;
    int n1 = n1b + sb;
    float2 v = cmulf(sh[sb][0][k2], d_W[n1*k2]);
    out[k2*256 + n1] = v;
  }
}

__global__ void __launch_bounds__(256) k_fwd2(){
  __shared__ float2 sh[4][2][256];
  int tid = threadIdx.x, sub = tid>>6, lane = tid&63;
  int row = blockIdx.x*4 + sub;            // s*625 + k2
  int s = row / 625, k2 = row - s*625;
  const float2* in = d_work + s*LTOT + k2*256;
  for (int i = lane; i < 256; i += 64) sh[sub][0][i] = in[i];
  __syncthreads();
  fft256s<-1>(sh[sub][0], sh[sub][1], lane);
  float2* out = d_spec + s*LTOT + k2*256;
  for (int i = lane; i < 256; i += 64) out[i] = sh[sub][0][i];
}

// ---------------- fused inverse stage 1: all 8 bands ----------------
// Block: 128 threads = 8 rows (consecutive k2) x 16 lanes. One signal per block.
__global__ void __launch_bounds__(128) k_inv1_all(){
  __shared__ float2 shX[8][256];
  __shared__ float2 T[8][257];
  int tid = threadIdx.x;
  int row = tid >> 4, j = tid & 15;
  int g = blockIdx.x, s = blockIdx.y;
  int k2base = g*8;
  const float2* spec = d_spec + s*LTOT;
  for (int t = tid; t < 8*256; t += 128){
    int rr = t >> 8, i = t & 255;
    int k2l = k2base + rr;
    shX[rr][i] = (k2l < 625) ? spec[k2l*256 + i] : make_float2(0.f,0.f);
  }
  __syncthreads();
  int k2 = k2base + row;
  bool rowok = (k2 < 625);
  int k2v = rowok ? k2 : 0;

  for (int b = 0; b < 8; b++){
    // ---- stage 1 (sparse: only r in {b, 15-b} nonzero for k2>=1) ----
    if (k2v == 0 && rowok){
      unsigned bm = 0;
      #pragma unroll
      for (int r = 0; r < 16; r++){
        int k1 = j + 16*r;
        int bnd = (k1==0) ? 7 : (((k1<=128)? (k1-1) : (255-k1)) >> 4);
        if (bnd == b) bm |= 1u<<r;
      }
      #pragma unroll
      for (int so = 0; so < 16; so++){
        float2 acc = make_float2(0.f,0.f);
        #pragma unroll
        for (int r = 0; r < 16; r++){
          if (bm & (1u<<r)){
            float2 w = d_W16[(r*so)&15]; w.y = -w.y;   // conj -> inverse
            acc = cadd(acc, cmulf(shX[row][j+16*r], w));
          }
        }
        T[row][16*j + (so ^ j)] = acc;
      }
    } else {
      float2 xlo = shX[row][j + 16*b];
      float2 xhi = shX[row][j + 240 - 16*b];
      #pragma unroll
      for (int so = 0; so < 16; so++){
        float2 wl = d_W16[(b*so)&15];      wl.y = -wl.y;
        float2 wh = d_W16[((15-b)*so)&15]; wh.y = -wh.y;
        T[row][16*j + (so ^ j)] = cadd(cmulf(xlo, wl), cmulf(xhi, wh));
      }
    }
    __syncthreads();
    // ---- stage 2: u[r] = T[j + 16r] * conjW(625*r*j); dft16 -> y[j+16r] ----
    float2 u[16];
    #pragma unroll
    for (int r = 0; r < 16; r++){
      float2 x = T[row][16*r + (j ^ r)];
      int m = 625*r*j;
      if (m){ float2 w = d_W[m]; w.y = -w.y; x = cmulf(x,w); }
      u[r] = x;
    }
    dft16<1>(u);
    __syncthreads();                     // all T reads done
    // conj twiddle W_L^{-k2*n1}, stage linearly
    #pragma unroll
    for (int r = 0; r < 16; r++){
      int n1 = j + 16*r;
      float2 w = d_W[k2v*n1]; w.y = -w.y;
      T[row][n1] = cmulf(u[r], w);
    }
    __syncthreads();
    // coalesced store: consecutive k2 adjacent in d_work8
    float2* w8 = d_work8 + (size_t)(b*16 + s)*LTOT;
    for (int t = tid; t < 8*256; t += 128){
      int n1 = t >> 3, rr = t & 7;
      int k2w = k2base + rr;
      if (k2w < 625) w8[n1*625 + k2w] = T[rr][n1];
    }
    __syncthreads();
  }
}

// ---------------- fused inverse stage 2 + energies: all 128 (band,sig) ----------------
// Block: 128 threads, 5 rows (n1) x 25 lanes (125 active).
#define IROWS 5
__global__ void __launch_bounds__(128) k_inv2_all(){
  __shared__ float2 buf[IROWS][25*26];
  __shared__ float  Psh[IROWS][156];
  int tid = threadIdx.x;
  int row = tid / 25, lane = tid % 25;
  bool act = (tid < 125);
  int g = blockIdx.x;           // n1 group
  int bs = blockIdx.y;          // b*16 + s
  int n1 = g*IROWS + row;
  bool rowok = act && (n1 < 256);

  float2 u[25];
  if (act){
    const float2* src = d_work8 + (size_t)bs*LTOT + (size_t)(rowok ? n1 : 0)*625;
    float2 v[25];
    #pragma unroll
    for (int r=0;r<25;r++) v[r] = rowok ? src[lane + 25*r] : make_float2(0.f,0.f);
    dft25<1>(v);
    #pragma unroll
    for (int r=0;r<25;r++) buf[row][lane*26 + r] = v[r];   // elem 25*lane+r
  }
  __syncthreads();
  if (act){
    #pragma unroll
    for (int r=0;r<25;r++){
      float2 x = buf[row][r*26 + lane];                    // elem lane+25r
      int m = 256*r*lane;
      if (m){ float2 w = d_W[m]; w.y = -w.y; x = cmulf(x,w); }
      u[r] = x;
    }
    dft25<1>(u);                 // y[n2 = lane + 25r] = u[r]  (x L)
  }
  __syncthreads();               // buf reads done
  float* eArr = (float*)&buf[0][0];   // IROWS*625 floats fits in buf
  const float invL = 1.0f/160000.0f;
  if (act){
    #pragma unroll
    for (int r=0;r<25;r++){
      float y = u[r].x * invL;
      eArr[row*625 + lane + 25*r] = y*y;
    }
  }
  __syncthreads();
  for (int t = tid; t < IROWS*156; t += 128){
    int rr = t / 156, jb = t - rr*156;
    const float* e = eArr + rr*625 + 4*jb;
    Psh[rr][jb] = (e[0] + e[1]) + (e[2] + e[3]);
  }
  __syncthreads();
  for (int t = tid; t < IROWS*156; t += 128){
    int jb = t / IROWS, rr = t - jb*IROWS;
    int n1w = g*IROWS + rr;
    if (n1w < 256) d_P[((size_t)bs*NBLK + jb)*256 + n1w] = Psh[rr][jb];
  }
}

// Reduce partials over n1 (fixed order -> deterministic)
__global__ void k_red_all(){
  int idx = blockIdx.x*blockDim.x + threadIdx.x;
  if (idx < NBS*NBLK){
    const float4* p = (const float4*)(d_P + (size_t)idx*256);
    float sum = 0.f;
    #pragma unroll 8
    for (int i=0;i<64;i++){
      float4 v = p[i];
      sum += (v.x + v.y) + (v.z + v.w);
    }
    d_blk[idx] = sum;
  }
}

__global__ void k_diff_all(){
  int t = blockIdx.x*blockDim.x + threadIdx.x;
  if (t < NDIFF){
    int s = t / (8*NCH);
    int rem = t - s*(8*NCH);
    int b = rem / NCH, jb = rem - b*NCH;
    float ew = d_blk[(b*16+s)*NBLK + jb]   + d_blk[(b*16+s)*NBLK + jb + 1];
    float eo = d_blk[(b*16+s+8)*NBLK + jb] + d_blk[(b*16+s+8)*NBLK + jb + 1];
    float lw = 10.f*log10f(ew*(1.f/2048.f) + 1e-12f);
    float lo = 10.f*log10f(eo*(1.f/2048.f) + 1e-12f);
    d_diff[t] = lw - lo;                  // -0.691 cancels
  }
}

__global__ void __launch_bounds__(1024) k_final(float* __restrict__ out){
  __shared__ float smax[1024];
  __shared__ float ssum[1024];
  __shared__ float swt[1024];
  int tid = threadIdx.x;
  float m = -1e30f;
  for (int i = tid; i < NDIFF; i += 1024) m = fmaxf(m, d_diff[i]);
  smax[tid] = m; __syncthreads();
  for (int st = 512; st > 0; st >>= 1){
    if (tid < st) smax[tid] = fmaxf(smax[tid], smax[tid+st]);
    __syncthreads();
  }
  float mx = smax[0];
  float se = 0.f, sw = 0.f;
  for (int i = tid; i < NDIFF; i += 1024){
    float d = d_diff[i];
    float e = expf(d - mx);
    se += e;
    sw = fmaf(e, d, sw);
  }
  ssum[tid] = se; swt[tid] = sw; __syncthreads();
  for (int st = 512; st > 0; st >>= 1){
    if (tid < st){ ssum[tid] += ssum[tid+st]; swt[tid] += swt[tid+st]; }
    __syncthreads();
  }
  if (tid == 0) out[0] = swt[0] / ssum[0];
}

extern "C" void kernel_launch(void* const* d_in, const int* in_sizes, int n_in,
                              void* d_out, int out_size){
  const float* xw = (const float*)d_in[0];   // watermarked_signals [8,160000]
  const float* xo = (const float*)d_in[1];   // original_signals    [8,160000]
  float* out = (float*)d_out;

  k_genW<<<(LTOT+255)/256, 256>>>();
  k_fwd1<<<dim3(64,16), 512>>>(xw, xo);
  k_fwd2<<<2500, 256>>>();
  k_inv1_all<<<dim3(79,16), 128>>>();        // 79*8 = 632 >= 625 k2 rows
  k_inv2_all<<<dim3(52,NBS), 128>>>();       // 52*5 = 260 >= 256 n1 rows
  k_red_all<<<(NBS*NBLK+255)/256, 256>>>();
  k_diff_all<<<(NDIFF+255)/256, 256>>>();
  k_final<<<1, 1024>>>(out);
}

// round 3
// speedup vs baseline: 2.6422x; 1.6705x over previous
#include <cuda_runtime.h>

// TFLoudnessLoss: multi-band (8) loudness difference with softmax weighting.
// Four-step FFT:  n = n1 + 256*n2,  k = k2 + 625*k1   (L = 160000 = 256*625)
// Two-for-one packing:
//   Forward: z_s = xw[s] + i*xo[s]  (8 FFTs), unpack via conj symmetry.
//   Inverse: bands paired  C_pair = C_{2p} + i*C_{2p+1}  (band signals real),
//            so one IFFT16 stage2 + twiddle + IFFT625 per band PAIR;
//            Re^2 -> band 2p energy, Im^2 -> band 2p+1 energy.

#define LTOT 160000
#define NSIG 16
#define NBLK 156
#define NCH  155
#define NDIFF (8*8*155)
#define NBS 128            /* 8 bands x 16 signals */
#define NPAIR 64           /* 4 band-pairs x 16 signals */

__device__ float2 d_W[LTOT];              // e^{-2*pi*i*m/L}
__device__ float2 d_W16[16];
__device__ float2 d_W25[25];
__device__ float2 d_spec[NSIG*LTOT];      // Z (slots 0..7) then unpacked Xw(0..7)/Xo(8..15)
__device__ float2 d_work[8*LTOT];         // fwd intermediate [s][k2*256+n1]
__device__ float2 d_work8[(size_t)NPAIR*LTOT];  // inv intermediate [pb*16+s][n1*625+k2]
__device__ float  d_P[NBS*NBLK*256];      // partial block energies [bs][j][n1]
__device__ float  d_blk[NBS*NBLK];
__device__ float  d_diff[NDIFF];

__device__ __forceinline__ float2 cmulf(float2 a, float2 b){
  return make_float2(fmaf(a.x,b.x,-a.y*b.y), fmaf(a.x,b.y,a.y*b.x));
}
__device__ __forceinline__ float2 cadd(float2 a,float2 b){return make_float2(a.x+b.x,a.y+b.y);}
__device__ __forceinline__ float2 csub(float2 a,float2 b){return make_float2(a.x-b.x,a.y-b.y);}

__global__ void k_genW(){
  int m = blockIdx.x*blockDim.x + threadIdx.x;
  if (m < LTOT){
    float t = (float)((double)m / 80000.0);   // 2m/L
    float s, c;
    sincospif(t, &s, &c);
    d_W[m] = make_float2(c, -s);
  }
  if (blockIdx.x == 0 && threadIdx.x < 25){
    int q = threadIdx.x;
    if (q < 16){
      float s, c; sincospif(2.f*q/16.f, &s, &c);
      d_W16[q] = make_float2(c, -s);
    }
    float s, c; sincospif(2.f*q/25.f, &s, &c);
    d_W25[q] = make_float2(c, -s);
  }
}

template<int SIGN>
__device__ __forceinline__ void dft5(float2 v[5]){
  const float C1 = 0.30901699437494745f;
  const float S1 = 0.95105651629515353f;
  const float C2 = -0.80901699437494745f;
  const float S2 = 0.58778525229247314f;
  float2 w1 = make_float2(C1,  SIGN*S1);
  float2 w2 = make_float2(C2,  SIGN*S2);
  float2 w3 = make_float2(C2, -SIGN*S2);
  float2 w4 = make_float2(C1, -SIGN*S1);
  float2 o0 = cadd(cadd(v[0],v[1]), cadd(cadd(v[2],v[3]),v[4]));
  float2 o1 = cadd(v[0], cadd(cadd(cmulf(v[1],w1),cmulf(v[2],w2)), cadd(cmulf(v[3],w3),cmulf(v[4],w4))));
  float2 o2 = cadd(v[0], cadd(cadd(cmulf(v[1],w2),cmulf(v[2],w4)), cadd(cmulf(v[3],w1),cmulf(v[4],w3))));
  float2 o3 = cadd(v[0], cadd(cadd(cmulf(v[1],w3),cmulf(v[2],w1)), cadd(cmulf(v[3],w4),cmulf(v[4],w2))));
  float2 o4 = cadd(v[0], cadd(cadd(cmulf(v[1],w4),cmulf(v[2],w3)), cadd(cmulf(v[3],w2),cmulf(v[4],w1))));
  v[0]=o0; v[1]=o1; v[2]=o2; v[3]=o3; v[4]=o4;
}

template<int SIGN>
__device__ __forceinline__ void dft4(float2 v[4]){
  float2 s02 = cadd(v[0],v[2]), d02 = csub(v[0],v[2]);
  float2 s13 = cadd(v[1],v[3]), d13 = csub(v[1],v[3]);
  float2 id13 = make_float2(-d13.y, d13.x);
  float2 o0 = cadd(s02, s13);
  float2 o2 = csub(s02, s13);
  float2 o1, o3;
  if (SIGN < 0){ o1 = csub(d02, id13); o3 = cadd(d02, id13); }
  else         { o1 = cadd(d02, id13); o3 = csub(d02, id13); }
  v[0]=o0; v[1]=o1; v[2]=o2; v[3]=o3;
}

template<int SIGN>
__device__ __forceinline__ float2 wm16(int m){
  float2 w = d_W16[m & 15];
  if (SIGN > 0) w.y = -w.y;
  return w;
}

template<int SIGN>
__device__ __forceinline__ void dft16(float2 v[16]){
  float2 t[16];
  #pragma unroll
  for (int r0=0;r0<4;r0++){
    float2 a[4] = {v[r0], v[r0+4], v[r0+8], v[r0+12]};
    dft4<SIGN>(a);
    #pragma unroll
    for (int k0=0;k0<4;k0++)
      t[r0*4+k0] = (r0*k0) ? cmulf(a[k0], wm16<SIGN>(r0*k0)) : a[k0];
  }
  #pragma unroll
  for (int k0=0;k0<4;k0++){
    float2 b[4] = {t[k0], t[4+k0], t[8+k0], t[12+k0]};
    dft4<SIGN>(b);
    #pragma unroll
    for (int k1=0;k1<4;k1++) v[k0 + 4*k1] = b[k1];
  }
}

template<int SIGN>
__device__ __forceinline__ float2 wm25(int m){
  float2 w = d_W25[m];
  if (SIGN > 0) w.y = -w.y;
  return w;
}

template<int SIGN>
__device__ __forceinline__ void dft25(float2 v[25]){
  float2 t[25];
  #pragma unroll
  for (int r0=0;r0<5;r0++){
    float2 a[5] = {v[r0], v[r0+5], v[r0+10], v[r0+15], v[r0+20]};
    dft5<SIGN>(a);
    #pragma unroll
    for (int k0=0;k0<5;k0++)
      t[r0*5+k0] = (r0*k0) ? cmulf(a[k0], wm25<SIGN>(r0*k0)) : a[k0];
  }
  #pragma unroll
  for (int k0=0;k0<5;k0++){
    float2 b[5] = {t[k0], t[5+k0], t[10+k0], t[15+k0], t[20+k0]};
    dft5<SIGN>(b);
    #pragma unroll
    for (int k1=0;k1<5;k1++) v[k0+5*k1] = b[k1];
  }
}

// ---------------- forward path ----------------

template<int SIGN>
__device__ void fft625(float2* __restrict__ A, float2* __restrict__ B, int lane){
  float2* src = A; float2* dst = B;
  int Ns = 1;
  #pragma unroll
  for (int t=0;t<4;t++){
    if (lane < 125){
      int j = lane;
      int jNs = j % Ns;
      int f = LTOT/(Ns*5);
      float2 v[5];
      #pragma unroll
      for (int r=0;r<5;r++){
        float2 x = src[j + r*125];
        int m = r*jNs*f;
        if (m){
          float2 w = d_W[m];
          if (SIGN>0) w.y = -w.y;
          x = cmulf(x,w);
        }
        v[r]=x;
      }
      dft5<SIGN>(v);
      int idxD = (j/Ns)*(Ns*5) + jNs;
      #pragma unroll
      for (int r=0;r<5;r++) dst[idxD + r*Ns] = v[r];
    }
    __syncthreads();
    float2* tmp = src; src = dst; dst = tmp;
    Ns *= 5;
  }
}

template<int SIGN>
__device__ void fft256s(float2* __restrict__ A, float2* __restrict__ B, int lane){
  float2* src = A; float2* dst = B;
  int Ns = 1;
  #pragma unroll
  for (int t=0;t<4;t++){
    {
      int j = lane;
      int jNs = j % Ns;
      int f = LTOT/(Ns*4);
      float2 v[4];
      #pragma unroll
      for (int r=0;r<4;r++){
        float2 x = src[j + r*64];
        int m = r*jNs*f;
        if (m){
          float2 w = d_W[m];
          if (SIGN>0) w.y = -w.y;
          x = cmulf(x,w);
        }
        v[r]=x;
      }
      dft4<SIGN>(v);
      int idxD = (j/Ns)*(Ns*4) + jNs;
      #pragma unroll
      for (int r=0;r<4;r++) dst[idxD + r*Ns] = v[r];
    }
    __syncthreads();
    float2* tmp = src; src = dst; dst = tmp;
    Ns *= 4;
  }
}

// z = xw + i*xo : 8 packed signals
__global__ void __launch_bounds__(512) k_fwd1(const float* __restrict__ xw, const float* __restrict__ xo){
  __shared__ float2 sh[4][2][625];
  int tid = threadIdx.x;
  int sub = tid >> 7, lane = tid & 127;
  int n1b = blockIdx.x*4;
  int s   = blockIdx.y;             // 0..7
  const float* xa = xw + s*LTOT;
  const float* xb = xo + s*LTOT;
  for (int w = tid; w < 2500; w += 512){
    int n2 = w >> 2, sb = w & 3;
    int n = n1b + sb + 256*n2;
    sh[sb][0][n2] = make_float2(xa[n], xb[n]);
  }
  __syncthreads();
  fft625<-1>(sh[sub][0], sh[sub][1], lane);
  float2* out = d_work + s*LTOT;
  for (int w = tid; w < 2500; w += 512){
    int k2 = w >> 2, sb = w & 3;
    int n1 = n1b + sb;
    float2 v = cmulf(sh[sb][0][k2], d_W[n1*k2]);
    out[k2*256 + n1] = v;
  }
}

__global__ void __launch_bounds__(256) k_fwd2(){
  __shared__ float2 sh[4][2][256];
  int tid = threadIdx.x, sub = tid>>6, lane = tid&63;
  int row = blockIdx.x*4 + sub;            // s*625 + k2, s in [0,8)
  int s = row / 625, k2 = row - s*625;
  const float2* in = d_work + s*LTOT + k2*256;
  for (int i = lane; i < 256; i += 64) sh[sub][0][i] = in[i];
  __syncthreads();
  fft256s<-1>(sh[sub][0], sh[sub][1], lane);
  float2* out = d_spec + s*LTOT + k2*256;
  for (int i = lane; i < 256; i += 64) out[i] = sh[sub][0][i];
}

// Unpack: Xw = (Z + conj(Zr))/2 (in place, slot s), Xo = (Z - conj(Zr))/(2i) (slot s+8).
// Partner of (k2,k1) is (625-k2, 255-k1) for k2>=1; row 0 partners itself at (256-k1)&255.
__global__ void __launch_bounds__(256) k_unpack(){
  __shared__ float2 shA[256], shB[256];
  int t = threadIdx.x;
  int grp = blockIdx.x;           // 0..312
  int s = blockIdx.y;             // 0..7
  float2* base  = d_spec + s*LTOT;
  float2* baseO = d_spec + (s+8)*LTOT;
  if (grp == 0){
    shA[t] = base[t];
    __syncthreads();
    float2 z = shA[t];
    float2 r = shA[(256 - t) & 255];
    base[t]  = make_float2(0.5f*(z.x + r.x), 0.5f*(z.y - r.y));
    baseO[t] = make_float2(0.5f*(z.y + r.y), 0.5f*(r.x - z.x));
  } else {
    int k2 = grp, k2p = 625 - grp;
    shA[t] = base[k2*256 + t];
    shB[t] = base[k2p*256 + t];
    __syncthreads();
    {
      float2 z = shA[t], r = shB[255 - t];
      base [k2*256 + t] = make_float2(0.5f*(z.x + r.x), 0.5f*(z.y - r.y));
      baseO[k2*256 + t] = make_float2(0.5f*(z.y + r.y), 0.5f*(r.x - z.x));
    }
    {
      float2 z = shB[t], r = shA[255 - t];
      base [k2p*256 + t] = make_float2(0.5f*(z.x + r.x), 0.5f*(z.y - r.y));
      baseO[k2p*256 + t] = make_float2(0.5f*(z.y + r.y), 0.5f*(r.x - z.x));
    }
  }
}

// ---------------- fused inverse stage 1: 4 band PAIRS ----------------
// Block: 128 threads = 8 rows (consecutive k2) x 16 lanes. One signal per block.
__global__ void __launch_bounds__(128) k_inv1_all(){
  __shared__ float2 shX[8][256];
  __shared__ float2 T[8][257];
  int tid = threadIdx.x;
  int row = tid >> 4, j = tid & 15;
  int g = blockIdx.x, s = blockIdx.y;
  int k2base = g*8;
  const float2* spec = d_spec + s*LTOT;
  for (int t = tid; t < 8*256; t += 128){
    int rr = t >> 8, i = t & 255;
    int k2l = k2base + rr;
    shX[rr][i] = (k2l < 625) ? spec[k2l*256 + i] : make_float2(0.f,0.f);
  }
  __syncthreads();
  int k2 = k2base + row;
  bool rowok = (k2 < 625);
  int k2v = rowok ? k2 : 0;

  for (int pb = 0; pb < 4; pb++){
    int b1 = 2*pb, b2 = 2*pb + 1;
    // ---- stage 1 (band-dependent, sparse), pack C_b1 + i*C_b2 ----
    if (k2v == 0 && rowok){
      unsigned bm1 = 0, bm2 = 0;
      #pragma unroll
      for (int r = 0; r < 16; r++){
        int k1 = j + 16*r;
        int bnd = (k1==0) ? 7 : (((k1<=128)? (k1-1) : (255-k1)) >> 4);
        if (bnd == b1) bm1 |= 1u<<r;
        if (bnd == b2) bm2 |= 1u<<r;
      }
      #pragma unroll
      for (int so = 0; so < 16; so++){
        float2 a1 = make_float2(0.f,0.f), a2 = make_float2(0.f,0.f);
        #pragma unroll
        for (int r = 0; r < 16; r++){
          float2 w = d_W16[(r*so)&15]; w.y = -w.y;
          if (bm1 & (1u<<r)) a1 = cadd(a1, cmulf(shX[row][j+16*r], w));
          if (bm2 & (1u<<r)) a2 = cadd(a2, cmulf(shX[row][j+16*r], w));
        }
        T[row][16*j + (so ^ j)] = make_float2(a1.x - a2.y, a1.y + a2.x);
      }
    } else {
      float2 lo1 = shX[row][j + 16*b1];
      float2 hi1 = shX[row][j + 240 - 16*b1];
      float2 lo2 = shX[row][j + 16*b2];
      float2 hi2 = shX[row][j + 240 - 16*b2];
      #pragma unroll
      for (int so = 0; so < 16; so++){
        float2 wl1 = d_W16[(b1*so)&15];      wl1.y = -wl1.y;
        float2 wh1 = d_W16[((15-b1)*so)&15]; wh1.y = -wh1.y;
        float2 wl2 = d_W16[(b2*so)&15];      wl2.y = -wl2.y;
        float2 wh2 = d_W16[((15-b2)*so)&15]; wh2.y = -wh2.y;
        float2 a = cadd(cmulf(lo1, wl1), cmulf(hi1, wh1));
        float2 c = cadd(cmulf(lo2, wl2), cmulf(hi2, wh2));
        T[row][16*j + (so ^ j)] = make_float2(a.x - c.y, a.y + c.x);
      }
    }
    __syncthreads();
    // ---- stage 2 (band-independent, linear): one pass per pair ----
    float2 u[16];
    #pragma unroll
    for (int r = 0; r < 16; r++){
      float2 x = T[row][16*r + (j ^ r)];
      int m = 625*r*j;
      if (m){ float2 w = d_W[m]; w.y = -w.y; x = cmulf(x,w); }
      u[r] = x;
    }
    dft16<1>(u);
    __syncthreads();
    #pragma unroll
    for (int r = 0; r < 16; r++){
      int n1 = j + 16*r;
      float2 w = d_W[k2v*n1]; w.y = -w.y;
      T[row][n1] = cmulf(u[r], w);
    }
    __syncthreads();
    float2* w8 = d_work8 + (size_t)(pb*16 + s)*LTOT;
    for (int t = tid; t < 8*256; t += 128){
      int n1 = t >> 3, rr = t & 7;
      int k2w = k2base + rr;
      if (k2w < 625) w8[n1*625 + k2w] = T[rr][n1];
    }
    __syncthreads();
  }
}

// ---------------- fused inverse stage 2 + energies: 64 (pair,sig) ----------------
#define IROWS 5
__global__ void __launch_bounds__(128) k_inv2_all(){
  __shared__ float2 buf[IROWS][25*26];
  __shared__ float  Psh[2][IROWS][156];
  int tid = threadIdx.x;
  int row = tid / 25, lane = tid % 25;
  bool act = (tid < 125);
  int g = blockIdx.x;             // n1 group
  int pbs = blockIdx.y;           // pb*16 + s
  int pb = pbs >> 4, s = pbs & 15;
  int n1 = g*IROWS + row;
  bool rowok = act && (n1 < 256);

  float2 u[25];
  if (act){
    const float2* src = d_work8 + (size_t)pbs*LTOT + (size_t)(rowok ? n1 : 0)*625;
    float2 v[25];
    #pragma unroll
    for (int r=0;r<25;r++) v[r] = rowok ? src[lane + 25*r] : make_float2(0.f,0.f);
    dft25<1>(v);
    #pragma unroll
    for (int r=0;r<25;r++) buf[row][lane*26 + r] = v[r];
  }
  __syncthreads();
  if (act){
    #pragma unroll
    for (int r=0;r<25;r++){
      float2 x = buf[row][r*26 + lane];
      int m = 256*r*lane;
      if (m){ float2 w = d_W[m]; w.y = -w.y; x = cmulf(x,w); }
      u[r] = x;
    }
    dft25<1>(u);                 // y_b1 + i*y_b2 at n2 = lane + 25r  (x L)
  }
  __syncthreads();
  float* eR = (float*)&buf[0][0];           // IROWS*625 floats
  float* eI = eR + IROWS*625;               // IROWS*625 floats (total 6250 <= 6500)
  const float invL = 1.0f/160000.0f;
  if (act){
    #pragma unroll
    for (int r=0;r<25;r++){
      int n2 = lane + 25*r;
      float yr = u[r].x * invL;
      float yi = u[r].y * invL;
      eR[row*625 + n2] = yr*yr;
      eI[row*625 + n2] = yi*yi;
    }
  }
  __syncthreads();
  for (int t = tid; t < IROWS*156; t += 128){
    int rr = t / 156, jb = t - rr*156;
    const float* e0 = eR + rr*625 + 4*jb;
    const float* e1 = eI + rr*625 + 4*jb;
    Psh[0][rr][jb] = (e0[0] + e0[1]) + (e0[2] + e0[3]);
    Psh[1][rr][jb] = (e1[0] + e1[1]) + (e1[2] + e1[3]);
  }
  __syncthreads();
  int bs1 = (2*pb)*16 + s, bs2 = (2*pb+1)*16 + s;
  for (int t = tid; t < IROWS*156; t += 128){
    int jb = t / IROWS, rr = t - jb*IROWS;
    int n1w = g*IROWS + rr;
    if (n1w < 256){
      d_P[((size_t)bs1*NBLK + jb)*256 + n1w] = Psh[0][rr][jb];
      d_P[((size_t)bs2*NBLK + jb)*256 + n1w] = Psh[1][rr][jb];
    }
  }
}

__global__ void k_red_all(){
  int idx = blockIdx.x*blockDim.x + threadIdx.x;
  if (idx < NBS*NBLK){
    const float4* p = (const float4*)(d_P + (size_t)idx*256);
    float sum = 0.f;
    #pragma unroll 8
    for (int i=0;i<64;i++){
      float4 v = p[i];
      sum += (v.x + v.y) + (v.z + v.w);
    }
    d_blk[idx] = sum;
  }
}

__global__ void k_diff_all(){
  int t = blockIdx.x*blockDim.x + threadIdx.x;
  if (t < NDIFF){
    int s = t / (8*NCH);
    int rem = t - s*(8*NCH);
    int b = rem / NCH, jb = rem - b*NCH;
    float ew = d_blk[(b*16+s)*NBLK + jb]   + d_blk[(b*16+s)*NBLK + jb + 1];
    float eo = d_blk[(b*16+s+8)*NBLK + jb] + d_blk[(b*16+s+8)*NBLK + jb + 1];
    float lw = 10.f*log10f(ew*(1.f/2048.f) + 1e-12f);
    float lo = 10.f*log10f(eo*(1.f/2048.f) + 1e-12f);
    d_diff[t] = lw - lo;
  }
}

__global__ void __launch_bounds__(1024) k_final(float* __restrict__ out){
  __shared__ float smax[1024];
  __shared__ float ssum[1024];
  __shared__ float swt[1024];
  int tid = threadIdx.x;
  float m = -1e30f;
  for (int i = tid; i < NDIFF; i += 1024) m = fmaxf(m, d_diff[i]);
  smax[tid] = m; __syncthreads();
  for (int st = 512; st > 0; st >>= 1){
    if (tid < st) smax[tid] = fmaxf(smax[tid], smax[tid+st]);
    __syncthreads();
  }
  float mx = smax[0];
  float se = 0.f, sw = 0.f;
  for (int i = tid; i < NDIFF; i += 1024){
    float d = d_diff[i];
    float e = expf(d - mx);
    se += e;
    sw = fmaf(e, d, sw);
  }
  ssum[tid] = se; swt[tid] = sw; __syncthreads();
  for (int st = 512; st > 0; st >>= 1){
    if (tid < st){ ssum[tid] += ssum[tid+st]; swt[tid] += swt[tid+st]; }
    __syncthreads();
  }
  if (tid == 0) out[0] = swt[0] / ssum[0];
}

extern "C" void kernel_launch(void* const* d_in, const int* in_sizes, int n_in,
                              void* d_out, int out_size){
  const float* xw = (const float*)d_in[0];
  const float* xo = (const float*)d_in[1];
  float* out = (float*)d_out;

  k_genW<<<(LTOT+255)/256, 256>>>();
  k_fwd1<<<dim3(64,8), 512>>>(xw, xo);
  k_fwd2<<<1250, 256>>>();
  k_unpack<<<dim3(313,8), 256>>>();
  k_inv1_all<<<dim3(79,16), 128>>>();
  k_inv2_all<<<dim3(52,NPAIR), 128>>>();
  k_red_all<<<(NBS*NBLK+255)/256, 256>>>();
  k_diff_all<<<(NDIFF+255)/256, 256>>>();
  k_final<<<1, 1024>>>(out);
}

// round 4
// speedup vs baseline: 3.0960x; 1.1718x over previous
#include <cuda_runtime.h>

// TFLoudnessLoss: multi-band (8) loudness difference with softmax weighting.
// Four-step FFT:  n = n1 + 256*n2,  k = k2 + 625*k1   (L = 160000 = 256*625)
// Packing: z_s = xw[s] + i*xo[s] (8 packed signals). Band mask is conjugate-
// symmetric, so IFFT(mask_b * Z) = r_w + i*r_o directly (both real) -- no
// spectrum unpack needed. Re^2 -> watermarked energy, Im^2 -> original energy.
// Band structure: with k1 = j + 16 r, for k2>=1 band(k2+625*k1) = r<8 ? r : 15-r.

#define LTOT 160000
#define NBLK 156
#define NCH  155
#define NDIFF (8*8*155)
#define NBS 128            /* 8 bands x 16 signals (w:0-7, o:8-15) */
#define NPIPE 64           /* 8 bands x 8 packed signals */

__device__ float2 d_W[LTOT];              // e^{-2*pi*i*m/L}
__device__ float2 d_W16[16];
__device__ float2 d_W25[25];
__device__ float2 d_spec[8*LTOT];         // packed spectra Z [s][k2*256+k1]
__device__ float2 d_work[8*LTOT];         // fwd intermediate [s][k2*256+n1]
__device__ float2 d_work8[(size_t)NPIPE*LTOT];  // inv intermediate [b*8+s][n1*625+k2]
__device__ float  d_P[NBS*NBLK*256];      // partial block energies [bs][j][n1]
__device__ float  d_blk[NBS*NBLK];
__device__ float  d_diff[NDIFF];

__device__ __forceinline__ float2 cmulf(float2 a, float2 b){
  return make_float2(fmaf(a.x,b.x,-a.y*b.y), fmaf(a.x,b.y,a.y*b.x));
}
__device__ __forceinline__ float2 cadd(float2 a,float2 b){return make_float2(a.x+b.x,a.y+b.y);}
__device__ __forceinline__ float2 csub(float2 a,float2 b){return make_float2(a.x-b.x,a.y-b.y);}

__global__ void k_genW(){
  int m = blockIdx.x*blockDim.x + threadIdx.x;
  if (m < LTOT){
    float t = (float)((double)m / 80000.0);   // 2m/L
    float s, c;
    sincospif(t, &s, &c);
    d_W[m] = make_float2(c, -s);
  }
  if (blockIdx.x == 0 && threadIdx.x < 25){
    int q = threadIdx.x;
    if (q < 16){
      float s, c; sincospif(2.f*q/16.f, &s, &c);
      d_W16[q] = make_float2(c, -s);
    }
    float s, c; sincospif(2.f*q/25.f, &s, &c);
    d_W25[q] = make_float2(c, -s);
  }
}

template<int SIGN>
__device__ __forceinline__ void dft5(float2 v[5]){
  const float C1 = 0.30901699437494745f;
  const float S1 = 0.95105651629515353f;
  const float C2 = -0.80901699437494745f;
  const float S2 = 0.58778525229247314f;
  float2 w1 = make_float2(C1,  SIGN*S1);
  float2 w2 = make_float2(C2,  SIGN*S2);
  float2 w3 = make_float2(C2, -SIGN*S2);
  float2 w4 = make_float2(C1, -SIGN*S1);
  float2 o0 = cadd(cadd(v[0],v[1]), cadd(cadd(v[2],v[3]),v[4]));
  float2 o1 = cadd(v[0], cadd(cadd(cmulf(v[1],w1),cmulf(v[2],w2)), cadd(cmulf(v[3],w3),cmulf(v[4],w4))));
  float2 o2 = cadd(v[0], cadd(cadd(cmulf(v[1],w2),cmulf(v[2],w4)), cadd(cmulf(v[3],w1),cmulf(v[4],w3))));
  float2 o3 = cadd(v[0], cadd(cadd(cmulf(v[1],w3),cmulf(v[2],w1)), cadd(cmulf(v[3],w4),cmulf(v[4],w2))));
  float2 o4 = cadd(v[0], cadd(cadd(cmulf(v[1],w4),cmulf(v[2],w3)), cadd(cmulf(v[3],w2),cmulf(v[4],w1))));
  v[0]=o0; v[1]=o1; v[2]=o2; v[3]=o3; v[4]=o4;
}

template<int SIGN>
__device__ __forceinline__ void dft4(float2 v[4]){
  float2 s02 = cadd(v[0],v[2]), d02 = csub(v[0],v[2]);
  float2 s13 = cadd(v[1],v[3]), d13 = csub(v[1],v[3]);
  float2 id13 = make_float2(-d13.y, d13.x);
  float2 o0 = cadd(s02, s13);
  float2 o2 = csub(s02, s13);
  float2 o1, o3;
  if (SIGN < 0){ o1 = csub(d02, id13); o3 = cadd(d02, id13); }
  else         { o1 = cadd(d02, id13); o3 = csub(d02, id13); }
  v[0]=o0; v[1]=o1; v[2]=o2; v[3]=o3;
}

// inverse DFT16 using conj-W16 table in shared
__device__ __forceinline__ void dft16i_sh(float2 v[16], const float2* __restrict__ w16c){
  float2 t[16];
  #pragma unroll
  for (int r0=0;r0<4;r0++){
    float2 a[4] = {v[r0], v[r0+4], v[r0+8], v[r0+12]};
    dft4<1>(a);
    #pragma unroll
    for (int k0=0;k0<4;k0++)
      t[r0*4+k0] = (r0*k0) ? cmulf(a[k0], w16c[r0*k0]) : a[k0];
  }
  #pragma unroll
  for (int k0=0;k0<4;k0++){
    float2 b[4] = {t[k0], t[4+k0], t[8+k0], t[12+k0]};
    dft4<1>(b);
    #pragma unroll
    for (int k1=0;k1<4;k1++) v[k0 + 4*k1] = b[k1];
  }
}

// inverse DFT25 using conj-W25 table in shared
__device__ __forceinline__ void dft25i_sh(float2 v[25], const float2* __restrict__ w25c){
  float2 t[25];
  #pragma unroll
  for (int r0=0;r0<5;r0++){
    float2 a[5] = {v[r0], v[r0+5], v[r0+10], v[r0+15], v[r0+20]};
    dft5<1>(a);
    #pragma unroll
    for (int k0=0;k0<5;k0++)
      t[r0*5+k0] = (r0*k0) ? cmulf(a[k0], w25c[r0*k0]) : a[k0];
  }
  #pragma unroll
  for (int k0=0;k0<5;k0++){
    float2 b[5] = {t[k0], t[5+k0], t[10+k0], t[15+k0], t[20+k0]};
    dft5<1>(b);
    #pragma unroll
    for (int k1=0;k1<5;k1++) v[k0+5*k1] = b[k1];
  }
}

// ---------------- forward path ----------------

template<int SIGN>
__device__ void fft625(float2* __restrict__ A, float2* __restrict__ B, int lane){
  float2* src = A; float2* dst = B;
  int Ns = 1;
  #pragma unroll
  for (int t=0;t<4;t++){
    if (lane < 125){
      int j = lane;
      int jNs = j % Ns;
      int f = LTOT/(Ns*5);
      float2 v[5];
      #pragma unroll
      for (int r=0;r<5;r++){
        float2 x = src[j + r*125];
        int m = r*jNs*f;
        if (m){
          float2 w = d_W[m];
          if (SIGN>0) w.y = -w.y;
          x = cmulf(x,w);
        }
        v[r]=x;
      }
      dft5<SIGN>(v);
      int idxD = (j/Ns)*(Ns*5) + jNs;
      #pragma unroll
      for (int r=0;r<5;r++) dst[idxD + r*Ns] = v[r];
    }
    __syncthreads();
    float2* tmp = src; src = dst; dst = tmp;
    Ns *= 5;
  }
}

template<int SIGN>
__device__ void fft256s(float2* __restrict__ A, float2* __restrict__ B, int lane){
  float2* src = A; float2* dst = B;
  int Ns = 1;
  #pragma unroll
  for (int t=0;t<4;t++){
    {
      int j = lane;
      int jNs = j % Ns;
      int f = LTOT/(Ns*4);
      float2 v[4];
      #pragma unroll
      for (int r=0;r<4;r++){
        float2 x = src[j + r*64];
        int m = r*jNs*f;
        if (m){
          float2 w = d_W[m];
          if (SIGN>0) w.y = -w.y;
          x = cmulf(x,w);
        }
        v[r]=x;
      }
      dft4<SIGN>(v);
      int idxD = (j/Ns)*(Ns*4) + jNs;
      #pragma unroll
      for (int r=0;r<4;r++) dst[idxD + r*Ns] = v[r];
    }
    __syncthreads();
    float2* tmp = src; src = dst; dst = tmp;
    Ns *= 4;
  }
}

// z = xw + i*xo : 8 packed signals
__global__ void __launch_bounds__(512) k_fwd1(const float* __restrict__ xw, const float* __restrict__ xo){
  __shared__ float2 sh[4][2][625];
  int tid = threadIdx.x;
  int sub = tid >> 7, lane = tid & 127;
  int n1b = blockIdx.x*4;
  int s   = blockIdx.y;             // 0..7
  const float* xa = xw + s*LTOT;
  const float* xb = xo + s*LTOT;
  for (int w = tid; w < 2500; w += 512){
    int n2 = w >> 2, sb = w & 3;
    int n = n1b + sb + 256*n2;
    sh[sb][0][n2] = make_float2(xa[n], xb[n]);
  }
  __syncthreads();
  fft625<-1>(sh[sub][0], sh[sub][1], lane);
  float2* out = d_work + s*LTOT;
  for (int w = tid; w < 2500; w += 512){
    int k2 = w >> 2, sb = w & 3;
    int n1 = n1b + sb;
    float2 v = cmulf(sh[sb][0][k2], d_W[n1*k2]);
    out[k2*256 + n1] = v;
  }
}

__global__ void __launch_bounds__(256) k_fwd2(){
  __shared__ float2 sh[4][2][256];
  int tid = threadIdx.x, sub = tid>>6, lane = tid&63;
  int row = blockIdx.x*4 + sub;            // s*625 + k2, s in [0,8)
  int s = row / 625, k2 = row - s*625;
  const float2* in = d_work + s*LTOT + k2*256;
  for (int i = lane; i < 256; i += 64) sh[sub][0][i] = in[i];
  __syncthreads();
  fft256s<-1>(sh[sub][0], sh[sub][1], lane);
  float2* out = d_spec + s*LTOT + k2*256;
  for (int i = lane; i < 256; i += 64) out[i] = sh[sub][0][i];
}

// ---------------- inverse stage 1: 8 bands per block, packed signals ----------------
// Block: 128 threads = 8 rows (consecutive k2) x 16 lanes. One packed signal per block.
__global__ void __launch_bounds__(128) k_inv1_all(){
  __shared__ float2 T[8][257];
  __shared__ float2 shTw[8][256];    // conj W_L^{k2*n1}
  __shared__ float2 shW6[256];       // conj W_L^{625*r*j}  [r*16+j]
  __shared__ float2 shW16c[16];      // conj W_16
  int tid = threadIdx.x;
  int row = tid >> 4, j = tid & 15;
  int g = blockIdx.x, s = blockIdx.y;   // s in [0,8)
  int k2base = g*8;
  const float2* spec = d_spec + s*LTOT;

  for (int t = tid; t < 8*256; t += 128){
    int rr = t >> 8, i = t & 255;
    int k2l = k2base + rr;
    int k2c = (k2l < 625) ? k2l : 0;
    float2 w = d_W[k2c * i];
    shTw[rr][i] = make_float2(w.x, -w.y);
  }
  if (tid < 16){ float2 w = d_W16[tid]; shW16c[tid] = make_float2(w.x, -w.y); }
  for (int t = tid; t < 256; t += 128){
    int r = t >> 4, jj = t & 15;
    float2 w = d_W[625*r*jj];
    shW6[t] = make_float2(w.x, -w.y);
  }
  __syncthreads();

  int k2 = k2base + row;
  bool rowok = (k2 < 625);
  int k2v = rowok ? k2 : 0;
  const float2* srow = spec + k2v*256;

  for (int b = 0; b < 8; b++){
    // ---- stage 1 (band-dependent, sparse) ----
    if (k2v == 0 && rowok){
      // exact masked 16-term path (only the k2=0 row of block g=0)
      float2 xv[16];
      unsigned bm = 0;
      #pragma unroll
      for (int r = 0; r < 16; r++){
        int k1 = j + 16*r;
        int bnd = (k1==0) ? 7 : (((k1<=128)? (k1-1) : (255-k1)) >> 4);
        if (bnd == b) bm |= 1u<<r;
        xv[r] = srow[j + 16*r];
      }
      #pragma unroll
      for (int so = 0; so < 16; so++){
        float2 acc = make_float2(0.f,0.f);
        #pragma unroll
        for (int r = 0; r < 16; r++){
          if (bm & (1u<<r)) acc = cadd(acc, cmulf(xv[r], shW16c[(r*so)&15]));
        }
        T[row][16*j + (so ^ j)] = acc;
      }
    } else {
      float2 lo = srow[j + 16*b];
      float2 hi = srow[j + 240 - 16*b];
      #pragma unroll
      for (int so = 0; so < 16; so++){
        float2 wl = shW16c[(b*so)&15];
        float2 wh = shW16c[((15-b)*so)&15];
        T[row][16*j + (so ^ j)] = cadd(cmulf(lo, wl), cmulf(hi, wh));
      }
    }
    __syncthreads();
    // ---- stage 2 (band-independent): IFFT16 over r with twiddles ----
    float2 u[16];
    #pragma unroll
    for (int r = 0; r < 16; r++)
      u[r] = cmulf(T[row][16*r + (j ^ r)], shW6[r*16 + j]);
    dft16i_sh(u, shW16c);
    __syncthreads();
    #pragma unroll
    for (int r = 0; r < 16; r++){
      int n1 = j + 16*r;
      T[row][n1] = cmulf(u[r], shTw[row][n1]);
    }
    __syncthreads();
    float2* w8 = d_work8 + (size_t)(b*8 + s)*LTOT;
    for (int t = tid; t < 8*256; t += 128){
      int n1 = t >> 3, rr = t & 7;
      int k2w = k2base + rr;
      if (k2w < 625) w8[n1*625 + k2w] = T[rr][n1];
    }
    __syncthreads();
  }
}

// ---------------- inverse stage 2 + energies: 64 (band, packed signal) ----------------
#define IROWS 5
__global__ void __launch_bounds__(128) k_inv2_all(){
  __shared__ float2 buf[IROWS][25*26];
  __shared__ float  Psh[2][IROWS][156];
  __shared__ float2 shWL[625];       // conj W_L^{256*r*lane}  [r*25+lane]
  __shared__ float2 shW25c[25];      // conj W_25
  int tid = threadIdx.x;
  int row = tid / 25, lane = tid % 25;
  bool act = (tid < 125);
  int g = blockIdx.x;                // n1 group
  int bs8 = blockIdx.y;              // b*8 + s
  int b = bs8 >> 3, s = bs8 & 7;
  int n1 = g*IROWS + row;
  bool rowok = act && (n1 < 256);

  for (int t = tid; t < 625; t += 128){
    int r = t / 25, la = t - r*25;
    float2 w = d_W[256*r*la];
    shWL[t] = make_float2(w.x, -w.y);
  }
  if (tid < 25){ float2 w = d_W25[tid]; shW25c[tid] = make_float2(w.x, -w.y); }
  __syncthreads();

  float2 u[25];
  if (act){
    const float2* src = d_work8 + (size_t)bs8*LTOT + (size_t)(rowok ? n1 : 0)*625;
    float2 v[25];
    #pragma unroll
    for (int r=0;r<25;r++) v[r] = rowok ? src[lane + 25*r] : make_float2(0.f,0.f);
    dft25i_sh(v, shW25c);
    #pragma unroll
    for (int r=0;r<25;r++) buf[row][lane*26 + r] = v[r];
  }
  __syncthreads();
  if (act){
    #pragma unroll
    for (int r=0;r<25;r++)
      u[r] = cmulf(buf[row][r*26 + lane], shWL[r*25 + lane]);
    dft25i_sh(u, shW25c);            // y_w + i*y_o at n2 = lane + 25r  (x L)
  }
  __syncthreads();
  float* eR = (float*)&buf[0][0];
  float* eI = eR + IROWS*625;
  const float invL = 1.0f/160000.0f;
  if (act){
    #pragma unroll
    for (int r=0;r<25;r++){
      int n2 = lane + 25*r;
      float yr = u[r].x * invL;
      float yi = u[r].y * invL;
      eR[row*625 + n2] = yr*yr;
      eI[row*625 + n2] = yi*yi;
    }
  }
  __syncthreads();
  for (int t = tid; t < IROWS*156; t += 128){
    int rr = t / 156, jb = t - rr*156;
    const float* e0 = eR + rr*625 + 4*jb;
    const float* e1 = eI + rr*625 + 4*jb;
    Psh[0][rr][jb] = (e0[0] + e0[1]) + (e0[2] + e0[3]);
    Psh[1][rr][jb] = (e1[0] + e1[1]) + (e1[2] + e1[3]);
  }
  __syncthreads();
  int bs1 = b*16 + s;        // watermarked
  int bs2 = b*16 + s + 8;    // original
  for (int t = tid; t < IROWS*156; t += 128){
    int jb = t / IROWS, rr = t - jb*IROWS;
    int n1w = g*IROWS + rr;
    if (n1w < 256){
      d_P[((size_t)bs1*NBLK + jb)*256 + n1w] = Psh[0][rr][jb];
      d_P[((size_t)bs2*NBLK + jb)*256 + n1w] = Psh[1][rr][jb];
    }
  }
}

__global__ void k_red_all(){
  int idx = blockIdx.x*blockDim.x + threadIdx.x;
  if (idx < NBS*NBLK){
    const float4* p = (const float4*)(d_P + (size_t)idx*256);
    float sum = 0.f;
    #pragma unroll 8
    for (int i=0;i<64;i++){
      float4 v = p[i];
      sum += (v.x + v.y) + (v.z + v.w);
    }
    d_blk[idx] = sum;
  }
}

__global__ void k_diff_all(){
  int t = blockIdx.x*blockDim.x + threadIdx.x;
  if (t < NDIFF){
    int s = t / (8*NCH);
    int rem = t - s*(8*NCH);
    int b = rem / NCH, jb = rem - b*NCH;
    float ew = d_blk[(b*16+s)*NBLK + jb]   + d_blk[(b*16+s)*NBLK + jb + 1];
    float eo = d_blk[(b*16+s+8)*NBLK + jb] + d_blk[(b*16+s+8)*NBLK + jb + 1];
    float lw = 10.f*log10f(ew*(1.f/2048.f) + 1e-12f);
    float lo = 10.f*log10f(eo*(1.f/2048.f) + 1e-12f);
    d_diff[t] = lw - lo;
  }
}

__global__ void __launch_bounds__(1024) k_final(float* __restrict__ out){
  __shared__ float smax[1024];
  __shared__ float ssum[1024];
  __shared__ float swt[1024];
  int tid = threadIdx.x;
  float m = -1e30f;
  for (int i = tid; i < NDIFF; i += 1024) m = fmaxf(m, d_diff[i]);
  smax[tid] = m; __syncthreads();
  for (int st = 512; st > 0; st >>= 1){
    if (tid < st) smax[tid] = fmaxf(smax[tid], smax[tid+st]);
    __syncthreads();
  }
  float mx = smax[0];
  float se = 0.f, sw = 0.f;
  for (int i = tid; i < NDIFF; i += 1024){
    float d = d_diff[i];
    float e = expf(d - mx);
    se += e;
    sw = fmaf(e, d, sw);
  }
  ssum[tid] = se; swt[tid] = sw; __syncthreads();
  for (int st = 512; st > 0; st >>= 1){
    if (tid < st){ ssum[tid] += ssum[tid+st]; swt[tid] += swt[tid+st]; }
    __syncthreads();
  }
  if (tid == 0) out[0] = swt[0] / ssum[0];
}

extern "C" void kernel_launch(void* const* d_in, const int* in_sizes, int n_in,
                              void* d_out, int out_size){
  const float* xw = (const float*)d_in[0];
  const float* xo = (const float*)d_in[1];
  float* out = (float*)d_out;

  k_genW<<<(LTOT+255)/256, 256>>>();
  k_fwd1<<<dim3(64,8), 512>>>(xw, xo);
  k_fwd2<<<1250, 256>>>();
  k_inv1_all<<<dim3(79,8), 128>>>();       // 79*8 = 632 >= 625 k2 rows
  k_inv2_all<<<dim3(52,NPIPE), 128>>>();   // 52*5 = 260 >= 256 n1 rows
  k_red_all<<<(NBS*NBLK+255)/256, 256>>>();
  k_diff_all<<<(NDIFF+255)/256, 256>>>();
  k_final<<<1, 1024>>>(out);
}

// round 5
// speedup vs baseline: 3.2325x; 1.0441x over previous
#include <cuda_runtime.h>

// TFLoudnessLoss: multi-band (8) loudness difference with softmax weighting.
// Four-step FFT:  n = n1 + 256*n2,  k = k2 + 625*k1   (L = 160000 = 256*625)
// Packing: z_s = xw[s] + i*xo[s] (8 packed signals). Band mask is conjugate-
// symmetric, so IFFT(mask_b * Z) = r_w + i*r_o directly (both real).
// Band structure: with k1 = j + 16 r, for k2>=1 band(k2+625*k1) = r<8 ? r : 15-r.

#define LTOT 160000
#define NBLK 156
#define NCH  155
#define NDIFF (8*8*155)
#define NBS 128            /* 8 bands x 16 signals (w:0-7, o:8-15) */
#define NPIPE 64           /* 8 bands x 8 packed signals */

__device__ float2 d_W[LTOT];              // e^{-2*pi*i*m/L}
__device__ float2 d_W16[16];
__device__ float2 d_W25[25];
__device__ float2 d_spec[8*LTOT];         // packed spectra Z [s][k2*256+k1]
__device__ float2 d_work[8*LTOT];         // fwd intermediate [s][k2*256+n1]
__device__ float2 d_work8[(size_t)NPIPE*LTOT];  // inv intermediate [b*8+s][n1*625+k2]
__device__ float  d_P[NBS*NBLK*256];      // partial block energies [bs][j][n1]
__device__ float  d_blk[NBS*NBLK];
__device__ float  d_diff[NDIFF];

__device__ __forceinline__ float2 cmulf(float2 a, float2 b){
  return make_float2(fmaf(a.x,b.x,-a.y*b.y), fmaf(a.x,b.y,a.y*b.x));
}
__device__ __forceinline__ float2 cadd(float2 a,float2 b){return make_float2(a.x+b.x,a.y+b.y);}
__device__ __forceinline__ float2 csub(float2 a,float2 b){return make_float2(a.x-b.x,a.y-b.y);}

__global__ void k_genW(){
  int m = blockIdx.x*blockDim.x + threadIdx.x;
  if (m < LTOT){
    float t = (float)((double)m / 80000.0);   // 2m/L
    float s, c;
    sincospif(t, &s, &c);
    d_W[m] = make_float2(c, -s);
  }
  if (blockIdx.x == 0 && threadIdx.x < 25){
    int q = threadIdx.x;
    if (q < 16){
      float s, c; sincospif(2.f*q/16.f, &s, &c);
      d_W16[q] = make_float2(c, -s);
    }
    float s, c; sincospif(2.f*q/25.f, &s, &c);
    d_W25[q] = make_float2(c, -s);
  }
}

template<int SIGN>
__device__ __forceinline__ void dft5(float2 v[5]){
  const float C1 = 0.30901699437494745f;
  const float S1 = 0.95105651629515353f;
  const float C2 = -0.80901699437494745f;
  const float S2 = 0.58778525229247314f;
  float2 w1 = make_float2(C1,  SIGN*S1);
  float2 w2 = make_float2(C2,  SIGN*S2);
  float2 w3 = make_float2(C2, -SIGN*S2);
  float2 w4 = make_float2(C1, -SIGN*S1);
  float2 o0 = cadd(cadd(v[0],v[1]), cadd(cadd(v[2],v[3]),v[4]));
  float2 o1 = cadd(v[0], cadd(cadd(cmulf(v[1],w1),cmulf(v[2],w2)), cadd(cmulf(v[3],w3),cmulf(v[4],w4))));
  float2 o2 = cadd(v[0], cadd(cadd(cmulf(v[1],w2),cmulf(v[2],w4)), cadd(cmulf(v[3],w1),cmulf(v[4],w3))));
  float2 o3 = cadd(v[0], cadd(cadd(cmulf(v[1],w3),cmulf(v[2],w1)), cadd(cmulf(v[3],w4),cmulf(v[4],w2))));
  float2 o4 = cadd(v[0], cadd(cadd(cmulf(v[1],w4),cmulf(v[2],w3)), cadd(cmulf(v[3],w2),cmulf(v[4],w1))));
  v[0]=o0; v[1]=o1; v[2]=o2; v[3]=o3; v[4]=o4;
}

template<int SIGN>
__device__ __forceinline__ void dft4(float2 v[4]){
  float2 s02 = cadd(v[0],v[2]), d02 = csub(v[0],v[2]);
  float2 s13 = cadd(v[1],v[3]), d13 = csub(v[1],v[3]);
  float2 id13 = make_float2(-d13.y, d13.x);
  float2 o0 = cadd(s02, s13);
  float2 o2 = csub(s02, s13);
  float2 o1, o3;
  if (SIGN < 0){ o1 = csub(d02, id13); o3 = cadd(d02, id13); }
  else         { o1 = cadd(d02, id13); o3 = csub(d02, id13); }
  v[0]=o0; v[1]=o1; v[2]=o2; v[3]=o3;
}

// inverse DFT16 using conj-W16 table in shared
__device__ __forceinline__ void dft16i_sh(float2 v[16], const float2* __restrict__ w16c){
  float2 t[16];
  #pragma unroll
  for (int r0=0;r0<4;r0++){
    float2 a[4] = {v[r0], v[r0+4], v[r0+8], v[r0+12]};
    dft4<1>(a);
    #pragma unroll
    for (int k0=0;k0<4;k0++)
      t[r0*4+k0] = (r0*k0) ? cmulf(a[k0], w16c[r0*k0]) : a[k0];
  }
  #pragma unroll
  for (int k0=0;k0<4;k0++){
    float2 b[4] = {t[k0], t[4+k0], t[8+k0], t[12+k0]};
    dft4<1>(b);
    #pragma unroll
    for (int k1=0;k1<4;k1++) v[k0 + 4*k1] = b[k1];
  }
}

// inverse DFT25 using conj-W25 table in shared
__device__ __forceinline__ void dft25i_sh(float2 v[25], const float2* __restrict__ w25c){
  float2 t[25];
  #pragma unroll
  for (int r0=0;r0<5;r0++){
    float2 a[5] = {v[r0], v[r0+5], v[r0+10], v[r0+15], v[r0+20]};
    dft5<1>(a);
    #pragma unroll
    for (int k0=0;k0<5;k0++)
      t[r0*5+k0] = (r0*k0) ? cmulf(a[k0], w25c[r0*k0]) : a[k0];
  }
  #pragma unroll
  for (int k0=0;k0<5;k0++){
    float2 b[5] = {t[k0], t[5+k0], t[10+k0], t[15+k0], t[20+k0]};
    dft5<1>(b);
    #pragma unroll
    for (int k1=0;k1<5;k1++) v[k0+5*k1] = b[k1];
  }
}

// ---------------- forward path ----------------

template<int SIGN>
__device__ void fft625(float2* __restrict__ A, float2* __restrict__ B, int lane){
  float2* src = A; float2* dst = B;
  int Ns = 1;
  #pragma unroll
  for (int t=0;t<4;t++){
    if (lane < 125){
      int j = lane;
      int jNs = j % Ns;
      int f = LTOT/(Ns*5);
      float2 v[5];
      #pragma unroll
      for (int r=0;r<5;r++){
        float2 x = src[j + r*125];
        int m = r*jNs*f;
        if (m){
          float2 w = d_W[m];
          if (SIGN>0) w.y = -w.y;
          x = cmulf(x,w);
        }
        v[r]=x;
      }
      dft5<SIGN>(v);
      int idxD = (j/Ns)*(Ns*5) + jNs;
      #pragma unroll
      for (int r=0;r<5;r++) dst[idxD + r*Ns] = v[r];
    }
    __syncthreads();
    float2* tmp = src; src = dst; dst = tmp;
    Ns *= 5;
  }
}

template<int SIGN>
__device__ void fft256s(float2* __restrict__ A, float2* __restrict__ B, int lane){
  float2* src = A; float2* dst = B;
  int Ns = 1;
  #pragma unroll
  for (int t=0;t<4;t++){
    {
      int j = lane;
      int jNs = j % Ns;
      int f = LTOT/(Ns*4);
      float2 v[4];
      #pragma unroll
      for (int r=0;r<4;r++){
        float2 x = src[j + r*64];
        int m = r*jNs*f;
        if (m){
          float2 w = d_W[m];
          if (SIGN>0) w.y = -w.y;
          x = cmulf(x,w);
        }
        v[r]=x;
      }
      dft4<SIGN>(v);
      int idxD = (j/Ns)*(Ns*4) + jNs;
      #pragma unroll
      for (int r=0;r<4;r++) dst[idxD + r*Ns] = v[r];
    }
    __syncthreads();
    float2* tmp = src; src = dst; dst = tmp;
    Ns *= 4;
  }
}

// z = xw + i*xo : 8 packed signals
__global__ void __launch_bounds__(512) k_fwd1(const float* __restrict__ xw, const float* __restrict__ xo){
  __shared__ float2 sh[4][2][625];
  int tid = threadIdx.x;
  int sub = tid >> 7, lane = tid & 127;
  int n1b = blockIdx.x*4;
  int s   = blockIdx.y;             // 0..7
  const float* xa = xw + s*LTOT;
  const float* xb = xo + s*LTOT;
  for (int w = tid; w < 2500; w += 512){
    int n2 = w >> 2, sb = w & 3;
    int n = n1b + sb + 256*n2;
    sh[sb][0][n2] = make_float2(xa[n], xb[n]);
  }
  __syncthreads();
  fft625<-1>(sh[sub][0], sh[sub][1], lane);
  float2* out = d_work + s*LTOT;
  for (int w = tid; w < 2500; w += 512){
    int k2 = w >> 2, sb = w & 3;
    int n1 = n1b + sb;
    float2 v = cmulf(sh[sb][0][k2], d_W[n1*k2]);
    out[k2*256 + n1] = v;
  }
}

__global__ void __launch_bounds__(256) k_fwd2(){
  __shared__ float2 sh[4][2][256];
  int tid = threadIdx.x, sub = tid>>6, lane = tid&63;
  int row = blockIdx.x*4 + sub;            // s*625 + k2, s in [0,8)
  int s = row / 625, k2 = row - s*625;
  const float2* in = d_work + s*LTOT + k2*256;
  for (int i = lane; i < 256; i += 64) sh[sub][0][i] = in[i];
  __syncthreads();
  fft256s<-1>(sh[sub][0], sh[sub][1], lane);
  float2* out = d_spec + s*LTOT + k2*256;
  for (int i = lane; i < 256; i += 64) out[i] = sh[sub][0][i];
}

// ---------------- inverse stage 1: 8 bands per block, packed signals ----------------
// Block: 128 threads = 8 rows (consecutive k2) x 16 lanes. One packed signal per block.
// Spectrum row preloaded into registers; warp-local barriers; double-buffered T so the
// global store of band b overlaps compute of band b+1 (one block barrier per band).
__global__ void __launch_bounds__(128) k_inv1_all(){
  __shared__ float2 T[2][8][257];
  __shared__ float2 shTw[8][256];    // conj W_L^{k2*n1}
  __shared__ float2 shW6[256];       // conj W_L^{625*r*j}  [r*16+j]
  __shared__ float2 shW16c[16];      // conj W_16
  int tid = threadIdx.x;
  int row = tid >> 4, j = tid & 15;
  int g = blockIdx.x, s = blockIdx.y;   // s in [0,8)
  int k2base = g*8;
  const float2* spec = d_spec + s*LTOT;

  for (int t = tid; t < 8*256; t += 128){
    int rr = t >> 8, i = t & 255;
    int k2l = k2base + rr;
    int k2c = (k2l < 625) ? k2l : 0;
    float2 w = d_W[k2c * i];
    shTw[rr][i] = make_float2(w.x, -w.y);
  }
  if (tid < 16){ float2 w = d_W16[tid]; shW16c[tid] = make_float2(w.x, -w.y); }
  for (int t = tid; t < 256; t += 128){
    int r = t >> 4, jj = t & 15;
    float2 w = d_W[625*r*jj];
    shW6[t] = make_float2(w.x, -w.y);
  }

  int k2 = k2base + row;
  bool rowok = (k2 < 625);
  int k2v = rowok ? k2 : 0;
  const float2* srow = spec + k2v*256;

  // preload entire needed row slice (amortizes global latency once)
  float2 xv[16];
  #pragma unroll
  for (int r = 0; r < 16; r++) xv[r] = srow[j + 16*r];

  bool special = (k2v == 0 && rowok);
  __syncthreads();     // tables ready

  for (int b = 0; b < 8; b++){
    float2 (*Tc)[257] = T[b & 1];
    // ---- stage 1 (band-dependent, sparse) ----
    if (special){
      unsigned bm = 0;
      #pragma unroll
      for (int r = 0; r < 16; r++){
        int k1 = j + 16*r;
        int bnd = (k1==0) ? 7 : (((k1<=128)? (k1-1) : (255-k1)) >> 4);
        if (bnd == b) bm |= 1u<<r;
      }
      #pragma unroll
      for (int so = 0; so < 16; so++){
        float2 acc = make_float2(0.f,0.f);
        #pragma unroll
        for (int r = 0; r < 16; r++){
          if (bm & (1u<<r)) acc = cadd(acc, cmulf(xv[r], shW16c[(r*so)&15]));
        }
        Tc[row][16*j + (so ^ j)] = acc;
      }
    } else {
      float2 lo = xv[b];
      float2 hi = xv[15-b];
      #pragma unroll
      for (int so = 0; so < 16; so++){
        float2 wl = shW16c[(b*so)&15];
        float2 wh = shW16c[((15-b)*so)&15];
        Tc[row][16*j + (so ^ j)] = cadd(cmulf(lo, wl), cmulf(hi, wh));
      }
    }
    __syncwarp();      // T[row] exchanges are half-warp-local
    // ---- stage 2 (band-independent): IFFT16 over r with twiddles ----
    float2 u[16];
    #pragma unroll
    for (int r = 0; r < 16; r++)
      u[r] = cmulf(Tc[row][16*r + (j ^ r)], shW6[r*16 + j]);
    dft16i_sh(u, shW16c);
    __syncwarp();      // all reads of Tc done before overwrite
    #pragma unroll
    for (int r = 0; r < 16; r++){
      int n1 = j + 16*r;
      Tc[row][n1] = cmulf(u[r], shTw[row][n1]);
    }
    __syncthreads();   // Tc final visible block-wide for the store loop
    float2* w8 = d_work8 + (size_t)(b*8 + s)*LTOT;
    for (int t = tid; t < 8*256; t += 128){
      int n1 = t >> 3, rr = t & 7;
      int k2w = k2base + rr;
      if (k2w < 625) w8[n1*625 + k2w] = Tc[rr][n1];
    }
    // no barrier: next band uses the other T buffer; this buffer is reused only
    // after the next band's __syncthreads, by which time this store loop is done.
  }
}

// ---------------- inverse stage 2 + energies: 64 (band, packed signal) ----------------
#define IROWS 5
__global__ void __launch_bounds__(128) k_inv2_all(){
  __shared__ float2 buf[IROWS][25*26];
  __shared__ float  Psh[2][IROWS][156];
  __shared__ float2 shWL[625];       // conj W_L^{256*r*lane}  [r*25+lane]
  __shared__ float2 shW25c[25];      // conj W_25
  int tid = threadIdx.x;
  int row = tid / 25, lane = tid % 25;
  bool act = (tid < 125);
  int g = blockIdx.x;                // n1 group
  int bs8 = blockIdx.y;              // b*8 + s
  int b = bs8 >> 3, s = bs8 & 7;
  int n1 = g*IROWS + row;
  bool rowok = act && (n1 < 256);

  for (int t = tid; t < 625; t += 128){
    int r = t / 25, la = t - r*25;
    float2 w = d_W[256*r*la];
    shWL[t] = make_float2(w.x, -w.y);
  }
  if (tid < 25){ float2 w = d_W25[tid]; shW25c[tid] = make_float2(w.x, -w.y); }
  __syncthreads();

  float2 u[25];
  if (act){
    const float2* src = d_work8 + (size_t)bs8*LTOT + (size_t)(rowok ? n1 : 0)*625;
    float2 v[25];
    #pragma unroll
    for (int r=0;r<25;r++) v[r] = rowok ? src[lane + 25*r] : make_float2(0.f,0.f);
    dft25i_sh(v, shW25c);
    #pragma unroll
    for (int r=0;r<25;r++) buf[row][lane*26 + r] = v[r];
  }
  __syncthreads();
  if (act){
    #pragma unroll
    for (int r=0;r<25;r++)
      u[r] = cmulf(buf[row][r*26 + lane], shWL[r*25 + lane]);
    dft25i_sh(u, shW25c);            // y_w + i*y_o at n2 = lane + 25r  (x L)
  }
  __syncthreads();
  float* eR = (float*)&buf[0][0];
  float* eI = eR + IROWS*625;
  const float invL = 1.0f/160000.0f;
  if (act){
    #pragma unroll
    for (int r=0;r<25;r++){
      int n2 = lane + 25*r;
      float yr = u[r].x * invL;
      float yi = u[r].y * invL;
      eR[row*625 + n2] = yr*yr;
      eI[row*625 + n2] = yi*yi;
    }
  }
  __syncthreads();
  for (int t = tid; t < IROWS*156; t += 128){
    int rr = t / 156, jb = t - rr*156;
    const float* e0 = eR + rr*625 + 4*jb;
    const float* e1 = eI + rr*625 + 4*jb;
    Psh[0][rr][jb] = (e0[0] + e0[1]) + (e0[2] + e0[3]);
    Psh[1][rr][jb] = (e1[0] + e1[1]) + (e1[2] + e1[3]);
  }
  __syncthreads();
  int bs1 = b*16 + s;        // watermarked
  int bs2 = b*16 + s + 8;    // original
  for (int t = tid; t < IROWS*156; t += 128){
    int jb = t / IROWS, rr = t - jb*IROWS;
    int n1w = g*IROWS + rr;
    if (n1w < 256){
      d_P[((size_t)bs1*NBLK + jb)*256 + n1w] = Psh[0][rr][jb];
      d_P[((size_t)bs2*NBLK + jb)*256 + n1w] = Psh[1][rr][jb];
    }
  }
}

__global__ void k_red_all(){
  int idx = blockIdx.x*blockDim.x + threadIdx.x;
  if (idx < NBS*NBLK){
    const float4* p = (const float4*)(d_P + (size_t)idx*256);
    float sum = 0.f;
    #pragma unroll 8
    for (int i=0;i<64;i++){
      float4 v = p[i];
      sum += (v.x + v.y) + (v.z + v.w);
    }
    d_blk[idx] = sum;
  }
}

__global__ void k_diff_all(){
  int t = blockIdx.x*blockDim.x + threadIdx.x;
  if (t < NDIFF){
    int s = t / (8*NCH);
    int rem = t - s*(8*NCH);
    int b = rem / NCH, jb = rem - b*NCH;
    float ew = d_blk[(b*16+s)*NBLK + jb]   + d_blk[(b*16+s)*NBLK + jb + 1];
    float eo = d_blk[(b*16+s+8)*NBLK + jb] + d_blk[(b*16+s+8)*NBLK + jb + 1];
    float lw = 10.f*log10f(ew*(1.f/2048.f) + 1e-12f);
    float lo = 10.f*log10f(eo*(1.f/2048.f) + 1e-12f);
    d_diff[t] = lw - lo;
  }
}

__global__ void __launch_bounds__(1024) k_final(float* __restrict__ out){
  __shared__ float smax[1024];
  __shared__ float ssum[1024];
  __shared__ float swt[1024];
  int tid = threadIdx.x;
  float m = -1e30f;
  for (int i = tid; i < NDIFF; i += 1024) m = fmaxf(m, d_diff[i]);
  smax[tid] = m; __syncthreads();
  for (int st = 512; st > 0; st >>= 1){
    if (tid < st) smax[tid] = fmaxf(smax[tid], smax[tid+st]);
    __syncthreads();
  }
  float mx = smax[0];
  float se = 0.f, sw = 0.f;
  for (int i = tid; i < NDIFF; i += 1024){
    float d = d_diff[i];
    float e = expf(d - mx);
    se += e;
    sw = fmaf(e, d, sw);
  }
  ssum[tid] = se; swt[tid] = sw; __syncthreads();
  for (int st = 512; st > 0; st >>= 1){
    if (tid < st){ ssum[tid] += ssum[tid+st]; swt[tid] += swt[tid+st]; }
    __syncthreads();
  }
  if (tid == 0) out[0] = swt[0] / ssum[0];
}

extern "C" void kernel_launch(void* const* d_in, const int* in_sizes, int n_in,
                              void* d_out, int out_size){
  const float* xw = (const float*)d_in[0];
  const float* xo = (const float*)d_in[1];
  float* out = (float*)d_out;

  k_genW<<<(LTOT+255)/256, 256>>>();
  k_fwd1<<<dim3(64,8), 512>>>(xw, xo);
  k_fwd2<<<1250, 256>>>();
  k_inv1_all<<<dim3(79,8), 128>>>();       // 79*8 = 632 >= 625 k2 rows
  k_inv2_all<<<dim3(52,NPIPE), 128>>>();   // 52*5 = 260 >= 256 n1 rows
  k_red_all<<<(NBS*NBLK+255)/256, 256>>>();
  k_diff_all<<<(NDIFF+255)/256, 256>>>();
  k_final<<<1, 1024>>>(out);
}

// round 6
// speedup vs baseline: 3.3725x; 1.0433x over previous
#include <cuda_runtime.h>

// TFLoudnessLoss: multi-band (8) loudness difference with softmax weighting.
// Four-step FFT:  n = n1 + 256*n2,  k = k2 + 625*k1   (L = 160000 = 256*625)
// Packing: z_s = xw[s] + i*xo[s] (8 packed signals). Band mask is conjugate-
// symmetric, so IFFT(mask_b * Z) = r_w + i*r_o directly (both real).
// Band structure: with k1 = j + 16 r, for k2>=1 band(k2+625*k1) = r<8 ? r : 15-r.
// inv1 stage 2 (IFFT16) runs as two radix-4 passes in-place on lane-private
// shared slots (positions 16s+(j^s) are private per lane j) -> ~8 live regs.

#define LTOT 160000
#define NBLK 156
#define NCH  155
#define NDIFF (8*8*155)
#define NBS 128            /* 8 bands x 16 signals (w:0-7, o:8-15) */
#define NPIPE 64           /* 8 bands x 8 packed signals */
#define NG2  52            /* inv2 n1-groups: 52*5 >= 256 */

__device__ float2 d_W[LTOT];              // e^{-2*pi*i*m/L}
__device__ float2 d_W16[16];
__device__ float2 d_W25[25];
__device__ float2 d_spec[8*LTOT];         // packed spectra Z [s][k2*256+k1]
__device__ float2 d_work[8*LTOT];         // fwd intermediate [s][k2*256+n1]
__device__ float2 d_work8[(size_t)NPIPE*LTOT];  // inv intermediate [b*8+s][n1*625+k2]
__device__ float  d_P[NBS*NBLK*NG2];      // partial block energies [bs][jb][g]
__device__ float  d_blk[NBS*NBLK];
__device__ float  d_diff[NDIFF];

__device__ __forceinline__ float2 cmulf(float2 a, float2 b){
  return make_float2(fmaf(a.x,b.x,-a.y*b.y), fmaf(a.x,b.y,a.y*b.x));
}
__device__ __forceinline__ float2 cadd(float2 a,float2 b){return make_float2(a.x+b.x,a.y+b.y);}
__device__ __forceinline__ float2 csub(float2 a,float2 b){return make_float2(a.x-b.x,a.y-b.y);}

__global__ void k_genW(){
  int m = blockIdx.x*blockDim.x + threadIdx.x;
  if (m < LTOT){
    float t = (float)((double)m / 80000.0);   // 2m/L
    float s, c;
    sincospif(t, &s, &c);
    d_W[m] = make_float2(c, -s);
  }
  if (blockIdx.x == 0 && threadIdx.x < 25){
    int q = threadIdx.x;
    if (q < 16){
      float s, c; sincospif(2.f*q/16.f, &s, &c);
      d_W16[q] = make_float2(c, -s);
    }
    float s, c; sincospif(2.f*q/25.f, &s, &c);
    d_W25[q] = make_float2(c, -s);
  }
}

template<int SIGN>
__device__ __forceinline__ void dft5(float2 v[5]){
  const float C1 = 0.30901699437494745f;
  const float S1 = 0.95105651629515353f;
  const float C2 = -0.80901699437494745f;
  const float S2 = 0.58778525229247314f;
  float2 w1 = make_float2(C1,  SIGN*S1);
  float2 w2 = make_float2(C2,  SIGN*S2);
  float2 w3 = make_float2(C2, -SIGN*S2);
  float2 w4 = make_float2(C1, -SIGN*S1);
  float2 o0 = cadd(cadd(v[0],v[1]), cadd(cadd(v[2],v[3]),v[4]));
  float2 o1 = cadd(v[0], cadd(cadd(cmulf(v[1],w1),cmulf(v[2],w2)), cadd(cmulf(v[3],w3),cmulf(v[4],w4))));
  float2 o2 = cadd(v[0], cadd(cadd(cmulf(v[1],w2),cmulf(v[2],w4)), cadd(cmulf(v[3],w1),cmulf(v[4],w3))));
  float2 o3 = cadd(v[0], cadd(cadd(cmulf(v[1],w3),cmulf(v[2],w1)), cadd(cmulf(v[3],w4),cmulf(v[4],w2))));
  float2 o4 = cadd(v[0], cadd(cadd(cmulf(v[1],w4),cmulf(v[2],w3)), cadd(cmulf(v[3],w2),cmulf(v[4],w1))));
  v[0]=o0; v[1]=o1; v[2]=o2; v[3]=o3; v[4]=o4;
}

template<int SIGN>
__device__ __forceinline__ void dft4(float2 v[4]){
  float2 s02 = cadd(v[0],v[2]), d02 = csub(v[0],v[2]);
  float2 s13 = cadd(v[1],v[3]), d13 = csub(v[1],v[3]);
  float2 id13 = make_float2(-d13.y, d13.x);
  float2 o0 = cadd(s02, s13);
  float2 o2 = csub(s02, s13);
  float2 o1, o3;
  if (SIGN < 0){ o1 = csub(d02, id13); o3 = cadd(d02, id13); }
  else         { o1 = cadd(d02, id13); o3 = csub(d02, id13); }
  v[0]=o0; v[1]=o1; v[2]=o2; v[3]=o3;
}

// inverse DFT25 using conj-W25 table in shared
__device__ __forceinline__ void dft25i_sh(float2 v[25], const float2* __restrict__ w25c){
  float2 t[25];
  #pragma unroll
  for (int r0=0;r0<5;r0++){
    float2 a[5] = {v[r0], v[r0+5], v[r0+10], v[r0+15], v[r0+20]};
    dft5<1>(a);
    #pragma unroll
    for (int k0=0;k0<5;k0++)
      t[r0*5+k0] = (r0*k0) ? cmulf(a[k0], w25c[r0*k0]) : a[k0];
  }
  #pragma unroll
  for (int k0=0;k0<5;k0++){
    float2 b[5] = {t[k0], t[5+k0], t[10+k0], t[15+k0], t[20+k0]};
    dft5<1>(b);
    #pragma unroll
    for (int k1=0;k1<5;k1++) v[k0+5*k1] = b[k1];
  }
}

// ---------------- forward path ----------------

template<int SIGN>
__device__ void fft625(float2* __restrict__ A, float2* __restrict__ B, int lane){
  float2* src = A; float2* dst = B;
  int Ns = 1;
  #pragma unroll
  for (int t=0;t<4;t++){
    if (lane < 125){
      int j = lane;
      int jNs = j % Ns;
      int f = LTOT/(Ns*5);
      float2 v[5];
      #pragma unroll
      for (int r=0;r<5;r++){
        float2 x = src[j + r*125];
        int m = r*jNs*f;
        if (m){
          float2 w = d_W[m];
          if (SIGN>0) w.y = -w.y;
          x = cmulf(x,w);
        }
        v[r]=x;
      }
      dft5<SIGN>(v);
      int idxD = (j/Ns)*(Ns*5) + jNs;
      #pragma unroll
      for (int r=0;r<5;r++) dst[idxD + r*Ns] = v[r];
    }
    __syncthreads();
    float2* tmp = src; src = dst; dst = tmp;
    Ns *= 5;
  }
}

template<int SIGN>
__device__ void fft256s(float2* __restrict__ A, float2* __restrict__ B, int lane){
  float2* src = A; float2* dst = B;
  int Ns = 1;
  #pragma unroll
  for (int t=0;t<4;t++){
    {
      int j = lane;
      int jNs = j % Ns;
      int f = LTOT/(Ns*4);
      float2 v[4];
      #pragma unroll
      for (int r=0;r<4;r++){
        float2 x = src[j + r*64];
        int m = r*jNs*f;
        if (m){
          float2 w = d_W[m];
          if (SIGN>0) w.y = -w.y;
          x = cmulf(x,w);
        }
        v[r]=x;
      }
      dft4<SIGN>(v);
      int idxD = (j/Ns)*(Ns*4) + jNs;
      #pragma unroll
      for (int r=0;r<4;r++) dst[idxD + r*Ns] = v[r];
    }
    __syncthreads();
    float2* tmp = src; src = dst; dst = tmp;
    Ns *= 4;
  }
}

// z = xw + i*xo : 8 packed signals
__global__ void __launch_bounds__(512) k_fwd1(const float* __restrict__ xw, const float* __restrict__ xo){
  __shared__ float2 sh[4][2][625];
  int tid = threadIdx.x;
  int sub = tid >> 7, lane = tid & 127;
  int n1b = blockIdx.x*4;
  int s   = blockIdx.y;             // 0..7
  const float* xa = xw + s*LTOT;
  const float* xb = xo + s*LTOT;
  for (int w = tid; w < 2500; w += 512){
    int n2 = w >> 2, sb = w & 3;
    int n = n1b + sb + 256*n2;
    sh[sb][0][n2] = make_float2(xa[n], xb[n]);
  }
  __syncthreads();
  fft625<-1>(sh[sub][0], sh[sub][1], lane);
  float2* out = d_work + s*LTOT;
  for (int w = tid; w < 2500; w += 512){
    int k2 = w >> 2, sb = w & 3;
    int n1 = n1b + sb;
    float2 v = cmulf(sh[sb][0][k2], d_W[n1*k2]);
    out[k2*256 + n1] = v;
  }
}

__global__ void __launch_bounds__(256) k_fwd2(){
  __shared__ float2 sh[4][2][256];
  int tid = threadIdx.x, sub = tid>>6, lane = tid&63;
  int row = blockIdx.x*4 + sub;            // s*625 + k2, s in [0,8)
  int s = row / 625, k2 = row - s*625;
  const float2* in = d_work + s*LTOT + k2*256;
  for (int i = lane; i < 256; i += 64) sh[sub][0][i] = in[i];
  __syncthreads();
  fft256s<-1>(sh[sub][0], sh[sub][1], lane);
  float2* out = d_spec + s*LTOT + k2*256;
  for (int i = lane; i < 256; i += 64) out[i] = sh[sub][0][i];
}

// ---------------- inverse stage 1: 8 bands per block, packed signals ----------------
// Block: 128 threads = 8 rows (consecutive k2) x 16 lanes. One packed signal per block.
// Stage-2 IFFT16 as two in-place radix-4 passes on lane-private shared slots.
__global__ void __launch_bounds__(128, 6) k_inv1_all(){
  __shared__ float2 T[8][257];
  __shared__ float2 shTw[8][256];    // conj W_L^{k2*n1}
  __shared__ float2 shW6[256];       // conj W_L^{625*r*j}  [r*16+j]
  __shared__ float2 shW16c[16];      // conj W_16
  int tid = threadIdx.x;
  int row = tid >> 4, j = tid & 15;
  int g = blockIdx.x, s = blockIdx.y;   // s in [0,8)
  int k2base = g*8;
  const float2* spec = d_spec + s*LTOT;

  for (int t = tid; t < 8*256; t += 128){
    int rr = t >> 8, i = t & 255;
    int k2l = k2base + rr;
    int k2c = (k2l < 625) ? k2l : 0;
    float2 w = d_W[k2c * i];
    shTw[rr][i] = make_float2(w.x, -w.y);
  }
  if (tid < 16){ float2 w = d_W16[tid]; shW16c[tid] = make_float2(w.x, -w.y); }
  for (int t = tid; t < 256; t += 128){
    int r = t >> 4, jj = t & 15;
    float2 w = d_W[625*r*jj];
    shW6[t] = make_float2(w.x, -w.y);
  }

  int k2 = k2base + row;
  bool rowok = (k2 < 625);
  int k2v = rowok ? k2 : 0;
  const float2* srow = spec + k2v*256;
  bool special = (k2v == 0 && rowok);
  __syncthreads();     // tables ready

  for (int b = 0; b < 8; b++){
    // ---- stage 1 (band-dependent, sparse) ----
    if (special){
      unsigned bm = 0;
      #pragma unroll
      for (int r = 0; r < 16; r++){
        int k1 = j + 16*r;
        int bnd = (k1==0) ? 7 : (((k1<=128)? (k1-1) : (255-k1)) >> 4);
        if (bnd == b) bm |= 1u<<r;
      }
      for (int so = 0; so < 16; so++){
        float2 acc = make_float2(0.f,0.f);
        for (int r = 0; r < 16; r++){
          if (bm & (1u<<r)) acc = cadd(acc, cmulf(srow[j+16*r], shW16c[(r*so)&15]));
        }
        T[row][16*j + (so ^ j)] = acc;
      }
    } else {
      float2 lo = srow[j + 16*b];
      float2 hi = srow[j + 240 - 16*b];
      #pragma unroll
      for (int so = 0; so < 16; so++){
        float2 wl = shW16c[(b*so)&15];
        float2 wh = shW16c[((15-b)*so)&15];
        T[row][16*j + (so ^ j)] = cadd(cmulf(lo, wl), cmulf(hi, wh));
      }
    }
    __syncwarp();      // cross-lane transpose within half-warp row

    // ---- stage 2: IFFT16 over r, in-place on lane-private slots ----
    // pass A: c[r0][k0] = dft4inv_{r2}(A[r0+4r2])[k0] * Wc16^{r0 k0} -> slot 4k0+r0
    #pragma unroll
    for (int r0 = 0; r0 < 4; r0++){
      float2 v[4];
      #pragma unroll
      for (int r2 = 0; r2 < 4; r2++){
        int r = r0 + 4*r2;
        v[r2] = cmulf(T[row][16*r + (j ^ r)], shW6[r*16 + j]);
      }
      dft4<1>(v);
      #pragma unroll
      for (int k0 = 0; k0 < 4; k0++){
        float2 c = (r0*k0) ? cmulf(v[k0], shW16c[(r0*k0)&15]) : v[k0];
        int sl = 4*k0 + r0;
        T[row][16*sl + (j ^ sl)] = c;
      }
    }
    // pass B: U[k0+4k1] = dft4inv_{r0}(c[r0][k0])[k1]; final twiddle; slot 4k0+k1
    #pragma unroll
    for (int k0 = 0; k0 < 4; k0++){
      float2 v[4];
      #pragma unroll
      for (int r0 = 0; r0 < 4; r0++){
        int sl = 4*k0 + r0;
        v[r0] = T[row][16*sl + (j ^ sl)];
      }
      dft4<1>(v);
      #pragma unroll
      for (int k1 = 0; k1 < 4; k1++){
        int q = k0 + 4*k1;
        int n1 = j + 16*q;
        float2 res = cmulf(v[k1], shTw[row][n1]);
        int sl = 4*k0 + k1;
        T[row][16*sl + (j ^ sl)] = res;
      }
    }
    __syncthreads();   // all rows final before cross-row coalesced store

    float2* w8 = d_work8 + (size_t)(b*8 + s)*LTOT;
    for (int t = tid; t < 8*256; t += 128){
      int n1 = t >> 3, rr = t & 7;
      int k2w = k2base + rr;
      int q = n1 >> 4;
      int sl = ((q & 3) << 2) | (q >> 2);      // value for q stored at slot 4(q&3)+(q>>2)
      int p = 16*sl + ((n1 & 15) ^ sl);
      if (k2w < 625) w8[n1*625 + k2w] = T[rr][p];
    }
    __syncthreads();   // T reusable by next band
  }
}

// ---------------- inverse stage 2 + energies: 64 (band, packed signal) ----------------
#define IROWS 5
__global__ void __launch_bounds__(128) k_inv2_all(){
  __shared__ float2 buf[IROWS][25*26];
  __shared__ float  Psh[2][IROWS][156];
  __shared__ float2 shWL[625];       // conj W_L^{256*r*lane}  [r*25+lane]
  __shared__ float2 shW25c[25];      // conj W_25
  int tid = threadIdx.x;
  int row = tid / 25, lane = tid % 25;
  bool act = (tid < 125);
  int g = blockIdx.x;                // n1 group
  int bs8 = blockIdx.y;              // b*8 + s
  int b = bs8 >> 3, s = bs8 & 7;
  int n1 = g*IROWS + row;
  bool rowok = act && (n1 < 256);

  for (int t = tid; t < 625; t += 128){
    int r = t / 25, la = t - r*25;
    float2 w = d_W[256*r*la];
    shWL[t] = make_float2(w.x, -w.y);
  }
  if (tid < 25){ float2 w = d_W25[tid]; shW25c[tid] = make_float2(w.x, -w.y); }
  __syncthreads();

  float2 u[25];
  if (act){
    const float2* src = d_work8 + (size_t)bs8*LTOT + (size_t)(rowok ? n1 : 0)*625;
    float2 v[25];
    #pragma unroll
    for (int r=0;r<25;r++) v[r] = rowok ? src[lane + 25*r] : make_float2(0.f,0.f);
    dft25i_sh(v, shW25c);
    #pragma unroll
    for (int r=0;r<25;r++) buf[row][lane*26 + r] = v[r];
  }
  __syncthreads();
  if (act){
    #pragma unroll
    for (int r=0;r<25;r++)
      u[r] = cmulf(buf[row][r*26 + lane], shWL[r*25 + lane]);
    dft25i_sh(u, shW25c);            // y_w + i*y_o at n2 = lane + 25r  (x L)
  }
  __syncthreads();
  float* eR = (float*)&buf[0][0];
  float* eI = eR + IROWS*625;
  const float invL = 1.0f/160000.0f;
  if (act){
    #pragma unroll
    for (int r=0;r<25;r++){
      int n2 = lane + 25*r;
      float yr = u[r].x * invL;
      float yi = u[r].y * invL;
      eR[row*625 + n2] = yr*yr;
      eI[row*625 + n2] = yi*yi;
    }
  }
  __syncthreads();
  for (int t = tid; t < IROWS*156; t += 128){
    int rr = t / 156, jb = t - rr*156;
    const float* e0 = eR + rr*625 + 4*jb;
    const float* e1 = eI + rr*625 + 4*jb;
    Psh[0][rr][jb] = (e0[0] + e0[1]) + (e0[2] + e0[3]);
    Psh[1][rr][jb] = (e1[0] + e1[1]) + (e1[2] + e1[3]);
  }
  __syncthreads();
  int bs1 = b*16 + s;        // watermarked
  int bs2 = b*16 + s + 8;    // original
  for (int t = tid; t < 2*156; t += 128){
    int half = t / 156, jb = t - half*156;
    float sum = ((Psh[half][0][jb] + Psh[half][1][jb]) +
                 (Psh[half][2][jb] + Psh[half][3][jb])) + Psh[half][4][jb];
    int bsx = half ? bs2 : bs1;
    d_P[((size_t)bsx*NBLK + jb)*NG2 + g] = sum;
  }
}

__global__ void k_red_all(){
  int idx = blockIdx.x*blockDim.x + threadIdx.x;
  if (idx < NBS*NBLK){
    const float* p = d_P + (size_t)idx*NG2;
    float sum = 0.f;
    #pragma unroll 4
    for (int i=0;i<NG2;i++) sum += p[i];
    d_blk[idx] = sum;
  }
}

__global__ void k_diff_all(){
  int t = blockIdx.x*blockDim.x + threadIdx.x;
  if (t < NDIFF){
    int s = t / (8*NCH);
    int rem = t - s*(8*NCH);
    int b = rem / NCH, jb = rem - b*NCH;
    float ew = d_blk[(b*16+s)*NBLK + jb]   + d_blk[(b*16+s)*NBLK + jb + 1];
    float eo = d_blk[(b*16+s+8)*NBLK + jb] + d_blk[(b*16+s+8)*NBLK + jb + 1];
    float lw = 10.f*log10f(ew*(1.f/2048.f) + 1e-12f);
    float lo = 10.f*log10f(eo*(1.f/2048.f) + 1e-12f);
    d_diff[t] = lw - lo;
  }
}

__global__ void __launch_bounds__(1024) k_final(float* __restrict__ out){
  __shared__ float smax[1024];
  __shared__ float ssum[1024];
  __shared__ float swt[1024];
  int tid = threadIdx.x;
  float m = -1e30f;
  for (int i = tid; i < NDIFF; i += 1024) m = fmaxf(m, d_diff[i]);
  smax[tid] = m; __syncthreads();
  for (int st = 512; st > 0; st >>= 1){
    if (tid < st) smax[tid] = fmaxf(smax[tid], smax[tid+st]);
    __syncthreads();
  }
  float mx = smax[0];
  float se = 0.f, sw = 0.f;
  for (int i = tid; i < NDIFF; i += 1024){
    float d = d_diff[i];
    float e = expf(d - mx);
    se += e;
    sw = fmaf(e, d, sw);
  }
  ssum[tid] = se; swt[tid] = sw; __syncthreads();
  for (int st = 512; st > 0; st >>= 1){
    if (tid < st){ ssum[tid] += ssum[tid+st]; swt[tid] += swt[tid+st]; }
    __syncthreads();
  }
  if (tid == 0) out[0] = swt[0] / ssum[0];
}

extern "C" void kernel_launch(void* const* d_in, const int* in_sizes, int n_in,
                              void* d_out, int out_size){
  const float* xw = (const float*)d_in[0];
  const float* xo = (const float*)d_in[1];
  float* out = (float*)d_out;

  k_genW<<<(LTOT+255)/256, 256>>>();
  k_fwd1<<<dim3(64,8), 512>>>(xw, xo);
  k_fwd2<<<1250, 256>>>();
  k_inv1_all<<<dim3(79,8), 128>>>();       // 79*8 = 632 >= 625 k2 rows
  k_inv2_all<<<dim3(NG2,NPIPE), 128>>>();  // 52*5 = 260 >= 256 n1 rows
  k_red_all<<<(NBS*NBLK+255)/256, 256>>>();
  k_diff_all<<<(NDIFF+255)/256, 256>>>();
  k_final<<<1, 1024>>>(out);
}

// round 7
// speedup vs baseline: 3.9768x; 1.1792x over previous
#include <cuda_runtime.h>

// TFLoudnessLoss: multi-band (8) loudness difference with softmax weighting.
// Four-step FFT:  n = n1 + 256*n2,  k = k2 + 625*k1   (L = 160000 = 256*625)
// Packing: z_s = xw[s] + i*xo[s] (8 packed signals). Band mask is conjugate-
// symmetric, so IFFT(mask_b * Z) = r_w + i*r_o directly (both real).
// Band structure: with k1 = j + 16 r, for k2>=1 band(k2+625*k1) = r<8 ? r : 15-r.
// inv1: grid (79 k2-groups, 8 signals, 4 band-pairs); final twiddle factored
// as W^{k2*(n1&15)} * W^{k2*16*(n1>>4)} (2KB tables instead of 16KB).

#define LTOT 160000
#define NBLK 156
#define NCH  155
#define NDIFF (8*8*155)
#define NBS 128            /* 8 bands x 16 signals (w:0-7, o:8-15) */
#define NPIPE 64           /* 8 bands x 8 packed signals */
#define NG2  52            /* inv2 n1-groups: 52*5 >= 256 */

__device__ float2 d_W[LTOT];              // e^{-2*pi*i*m/L}
__device__ float2 d_W16[16];
__device__ float2 d_W25[25];
__device__ float2 d_spec[8*LTOT];         // packed spectra Z [s][k2*256+k1]
__device__ float2 d_work[8*LTOT];         // fwd intermediate [s][k2*256+n1]
__device__ float2 d_work8[(size_t)NPIPE*LTOT];  // inv intermediate [b*8+s][n1*625+k2]
__device__ float  d_P[NBS*NBLK*NG2];      // partial block energies [bs][jb][g]
__device__ float  d_blk[NBS*NBLK];
__device__ float  d_diff[NDIFF];

__device__ __forceinline__ float2 cmulf(float2 a, float2 b){
  return make_float2(fmaf(a.x,b.x,-a.y*b.y), fmaf(a.x,b.y,a.y*b.x));
}
__device__ __forceinline__ float2 cadd(float2 a,float2 b){return make_float2(a.x+b.x,a.y+b.y);}
__device__ __forceinline__ float2 csub(float2 a,float2 b){return make_float2(a.x-b.x,a.y-b.y);}

__global__ void k_genW(){
  int m = blockIdx.x*blockDim.x + threadIdx.x;
  if (m < LTOT){
    float t = (float)((double)m / 80000.0);   // 2m/L
    float s, c;
    sincospif(t, &s, &c);
    d_W[m] = make_float2(c, -s);
  }
  if (blockIdx.x == 0 && threadIdx.x < 25){
    int q = threadIdx.x;
    if (q < 16){
      float s, c; sincospif(2.f*q/16.f, &s, &c);
      d_W16[q] = make_float2(c, -s);
    }
    float s, c; sincospif(2.f*q/25.f, &s, &c);
    d_W25[q] = make_float2(c, -s);
  }
}

template<int SIGN>
__device__ __forceinline__ void dft5(float2 v[5]){
  const float C1 = 0.30901699437494745f;
  const float S1 = 0.95105651629515353f;
  const float C2 = -0.80901699437494745f;
  const float S2 = 0.58778525229247314f;
  float2 w1 = make_float2(C1,  SIGN*S1);
  float2 w2 = make_float2(C2,  SIGN*S2);
  float2 w3 = make_float2(C2, -SIGN*S2);
  float2 w4 = make_float2(C1, -SIGN*S1);
  float2 o0 = cadd(cadd(v[0],v[1]), cadd(cadd(v[2],v[3]),v[4]));
  float2 o1 = cadd(v[0], cadd(cadd(cmulf(v[1],w1),cmulf(v[2],w2)), cadd(cmulf(v[3],w3),cmulf(v[4],w4))));
  float2 o2 = cadd(v[0], cadd(cadd(cmulf(v[1],w2),cmulf(v[2],w4)), cadd(cmulf(v[3],w1),cmulf(v[4],w3))));
  float2 o3 = cadd(v[0], cadd(cadd(cmulf(v[1],w3),cmulf(v[2],w1)), cadd(cmulf(v[3],w4),cmulf(v[4],w2))));
  float2 o4 = cadd(v[0], cadd(cadd(cmulf(v[1],w4),cmulf(v[2],w3)), cadd(cmulf(v[3],w2),cmulf(v[4],w1))));
  v[0]=o0; v[1]=o1; v[2]=o2; v[3]=o3; v[4]=o4;
}

template<int SIGN>
__device__ __forceinline__ void dft4(float2 v[4]){
  float2 s02 = cadd(v[0],v[2]), d02 = csub(v[0],v[2]);
  float2 s13 = cadd(v[1],v[3]), d13 = csub(v[1],v[3]);
  float2 id13 = make_float2(-d13.y, d13.x);
  float2 o0 = cadd(s02, s13);
  float2 o2 = csub(s02, s13);
  float2 o1, o3;
  if (SIGN < 0){ o1 = csub(d02, id13); o3 = cadd(d02, id13); }
  else         { o1 = cadd(d02, id13); o3 = csub(d02, id13); }
  v[0]=o0; v[1]=o1; v[2]=o2; v[3]=o3;
}

// inverse DFT25 using conj-W25 table in shared
__device__ __forceinline__ void dft25i_sh(float2 v[25], const float2* __restrict__ w25c){
  float2 t[25];
  #pragma unroll
  for (int r0=0;r0<5;r0++){
    float2 a[5] = {v[r0], v[r0+5], v[r0+10], v[r0+15], v[r0+20]};
    dft5<1>(a);
    #pragma unroll
    for (int k0=0;k0<5;k0++)
      t[r0*5+k0] = (r0*k0) ? cmulf(a[k0], w25c[r0*k0]) : a[k0];
  }
  #pragma unroll
  for (int k0=0;k0<5;k0++){
    float2 b[5] = {t[k0], t[5+k0], t[10+k0], t[15+k0], t[20+k0]};
    dft5<1>(b);
    #pragma unroll
    for (int k1=0;k1<5;k1++) v[k0+5*k1] = b[k1];
  }
}

// ---------------- forward path ----------------

template<int SIGN>
__device__ void fft625(float2* __restrict__ A, float2* __restrict__ B, int lane){
  float2* src = A; float2* dst = B;
  int Ns = 1;
  #pragma unroll
  for (int t=0;t<4;t++){
    if (lane < 125){
      int j = lane;
      int jNs = j % Ns;
      int f = LTOT/(Ns*5);
      float2 v[5];
      #pragma unroll
      for (int r=0;r<5;r++){
        float2 x = src[j + r*125];
        int m = r*jNs*f;
        if (m){
          float2 w = d_W[m];
          if (SIGN>0) w.y = -w.y;
          x = cmulf(x,w);
        }
        v[r]=x;
      }
      dft5<SIGN>(v);
      int idxD = (j/Ns)*(Ns*5) + jNs;
      #pragma unroll
      for (int r=0;r<5;r++) dst[idxD + r*Ns] = v[r];
    }
    __syncthreads();
    float2* tmp = src; src = dst; dst = tmp;
    Ns *= 5;
  }
}

template<int SIGN>
__device__ void fft256s(float2* __restrict__ A, float2* __restrict__ B, int lane){
  float2* src = A; float2* dst = B;
  int Ns = 1;
  #pragma unroll
  for (int t=0;t<4;t++){
    {
      int j = lane;
      int jNs = j % Ns;
      int f = LTOT/(Ns*4);
      float2 v[4];
      #pragma unroll
      for (int r=0;r<4;r++){
        float2 x = src[j + r*64];
        int m = r*jNs*f;
        if (m){
          float2 w = d_W[m];
          if (SIGN>0) w.y = -w.y;
          x = cmulf(x,w);
        }
        v[r]=x;
      }
      dft4<SIGN>(v);
      int idxD = (j/Ns)*(Ns*4) + jNs;
      #pragma unroll
      for (int r=0;r<4;r++) dst[idxD + r*Ns] = v[r];
    }
    __syncthreads();
    float2* tmp = src; src = dst; dst = tmp;
    Ns *= 4;
  }
}

// z = xw + i*xo : 8 packed signals
__global__ void __launch_bounds__(512) k_fwd1(const float* __restrict__ xw, const float* __restrict__ xo){
  __shared__ float2 sh[4][2][625];
  int tid = threadIdx.x;
  int sub = tid >> 7, lane = tid & 127;
  int n1b = blockIdx.x*4;
  int s   = blockIdx.y;             // 0..7
  const float* xa = xw + s*LTOT;
  const float* xb = xo + s*LTOT;
  for (int w = tid; w < 2500; w += 512){
    int n2 = w >> 2, sb = w & 3;
    int n = n1b + sb + 256*n2;
    sh[sb][0][n2] = make_float2(xa[n], xb[n]);
  }
  __syncthreads();
  fft625<-1>(sh[sub][0], sh[sub][1], lane);
  float2* out = d_work + s*LTOT;
  for (int w = tid; w < 2500; w += 512){
    int k2 = w >> 2, sb = w & 3;
    int n1 = n1b + sb;
    float2 v = cmulf(sh[sb][0][k2], d_W[n1*k2]);
    out[k2*256 + n1] = v;
  }
}

__global__ void __launch_bounds__(256) k_fwd2(){
  __shared__ float2 sh[4][2][256];
  int tid = threadIdx.x, sub = tid>>6, lane = tid&63;
  int row = blockIdx.x*4 + sub;            // s*625 + k2, s in [0,8)
  int s = row / 625, k2 = row - s*625;
  const float2* in = d_work + s*LTOT + k2*256;
  for (int i = lane; i < 256; i += 64) sh[sub][0][i] = in[i];
  __syncthreads();
  fft256s<-1>(sh[sub][0], sh[sub][1], lane);
  float2* out = d_spec + s*LTOT + k2*256;
  for (int i = lane; i < 256; i += 64) out[i] = sh[sub][0][i];
}

// ---------------- inverse stage 1: one band-PAIR per block ----------------
// Block: 128 threads = 8 rows (consecutive k2) x 16 lanes.
// Grid: (79 k2-groups, 8 signals, 4 band-pairs) = 2528 blocks.
// Stage-2 IFFT16 as two in-place radix-4 passes on lane-private shared slots.
__global__ void __launch_bounds__(128, 10) k_inv1_all(){
  __shared__ float2 T[8][257];       // ~16.4KB
  __shared__ float2 shW6[256];       // conj W_L^{625*r*j}  [r*16+j]
  __shared__ float2 shAc[8][16];     // conj W_L^{k2*l},    l<16
  __shared__ float2 shBc[8][16];     // conj W_L^{k2*16*h}, h<16
  __shared__ float2 shW16c[16];      // conj W_16
  int tid = threadIdx.x;
  int row = tid >> 4, j = tid & 15;
  int g = blockIdx.x, s = blockIdx.y, pz = blockIdx.z;
  int k2base = g*8;
  const float2* spec = d_spec + s*LTOT;

  if (tid < 16){ float2 w = d_W16[tid]; shW16c[tid] = make_float2(w.x, -w.y); }
  for (int t = tid; t < 256; t += 128){
    int r = t >> 4, jj = t & 15;
    float2 w = d_W[625*r*jj];
    shW6[t] = make_float2(w.x, -w.y);
  }
  {
    // per-row factored final twiddle tables (2 entries per thread)
    int rr = tid >> 4, e = tid & 15;
    int k2l = k2base + rr;
    int k2c = (k2l < 625) ? k2l : 0;
    float2 wa = d_W[k2c * e];
    float2 wb = d_W[k2c * 16 * e];
    shAc[rr][e] = make_float2(wa.x, -wa.y);
    shBc[rr][e] = make_float2(wb.x, -wb.y);
  }

  int k2 = k2base + row;
  bool rowok = (k2 < 625);
  int k2v = rowok ? k2 : 0;
  const float2* srow = spec + k2v*256;
  bool special = (k2v == 0 && rowok);
  __syncthreads();     // tables ready

  float2 acj;          // conj W^{k2*j} -- fixed per thread
  acj = shAc[row][j];

  #pragma unroll
  for (int bi = 0; bi < 2; bi++){
    int b = 2*pz + bi;
    // ---- stage 1 (band-dependent, sparse) ----
    if (special){
      unsigned bm = 0;
      #pragma unroll
      for (int r = 0; r < 16; r++){
        int k1 = j + 16*r;
        int bnd = (k1==0) ? 7 : (((k1<=128)? (k1-1) : (255-k1)) >> 4);
        if (bnd == b) bm |= 1u<<r;
      }
      for (int so = 0; so < 16; so++){
        float2 acc = make_float2(0.f,0.f);
        for (int r = 0; r < 16; r++){
          if (bm & (1u<<r)) acc = cadd(acc, cmulf(srow[j+16*r], shW16c[(r*so)&15]));
        }
        T[row][16*j + (so ^ j)] = acc;
      }
    } else {
      float2 lo = srow[j + 16*b];
      float2 hi = srow[j + 240 - 16*b];
      #pragma unroll
      for (int so = 0; so < 16; so++){
        float2 wl = shW16c[(b*so)&15];
        float2 wh = shW16c[((15-b)*so)&15];
        T[row][16*j + (so ^ j)] = cadd(cmulf(lo, wl), cmulf(hi, wh));
      }
    }
    __syncwarp();      // cross-lane transpose within half-warp row

    // ---- stage 2: IFFT16 over r, in-place on lane-private slots ----
    // pass A: c[r0][k0] = dft4inv_{r2}(A[r0+4r2])[k0] * Wc16^{r0 k0} -> slot 4k0+r0
    #pragma unroll
    for (int r0 = 0; r0 < 4; r0++){
      float2 v[4];
      #pragma unroll
      for (int r2 = 0; r2 < 4; r2++){
        int r = r0 + 4*r2;
        v[r2] = cmulf(T[row][16*r + (j ^ r)], shW6[r*16 + j]);
      }
      dft4<1>(v);
      #pragma unroll
      for (int k0 = 0; k0 < 4; k0++){
        float2 c = (r0*k0) ? cmulf(v[k0], shW16c[(r0*k0)&15]) : v[k0];
        int sl = 4*k0 + r0;
        T[row][16*sl + (j ^ sl)] = c;
      }
    }
    // pass B: U[k0+4k1] = dft4inv_{r0}(c[r0][k0])[k1]; final twiddle; slot 4k0+k1
    #pragma unroll
    for (int k0 = 0; k0 < 4; k0++){
      float2 v[4];
      #pragma unroll
      for (int r0 = 0; r0 < 4; r0++){
        int sl = 4*k0 + r0;
        v[r0] = T[row][16*sl + (j ^ sl)];
      }
      dft4<1>(v);
      #pragma unroll
      for (int k1 = 0; k1 < 4; k1++){
        int q = k0 + 4*k1;
        float2 tw = cmulf(acj, shBc[row][q]);   // conj W^{k2*(j+16q)}
        float2 res = cmulf(v[k1], tw);
        int sl = 4*k0 + k1;
        T[row][16*sl + (j ^ sl)] = res;
      }
    }
    __syncthreads();   // all rows final before cross-row coalesced store

    float2* w8 = d_work8 + (size_t)(b*8 + s)*LTOT;
    for (int t = tid; t < 8*256; t += 128){
      int n1 = t >> 3, rr = t & 7;
      int k2w = k2base + rr;
      int q = n1 >> 4;
      int sl = ((q & 3) << 2) | (q >> 2);      // value for q stored at slot 4(q&3)+(q>>2)
      int p = 16*sl + ((n1 & 15) ^ sl);
      if (k2w < 625) w8[n1*625 + k2w] = T[rr][p];
    }
    __syncthreads();   // T reusable by next band
  }
}

// ---------------- inverse stage 2 + energies: 64 (band, packed signal) ----------------
#define IROWS 5
__global__ void __launch_bounds__(128) k_inv2_all(){
  __shared__ float2 buf[IROWS][25*26];
  __shared__ float  Psh[2][IROWS][156];
  __shared__ float2 shWL[625];       // conj W_L^{256*r*lane}  [r*25+lane]
  __shared__ float2 shW25c[25];      // conj W_25
  int tid = threadIdx.x;
  int row = tid / 25, lane = tid % 25;
  bool act = (tid < 125);
  int g = blockIdx.x;                // n1 group
  int bs8 = blockIdx.y;              // b*8 + s
  int b = bs8 >> 3, s = bs8 & 7;
  int n1 = g*IROWS + row;
  bool rowok = act && (n1 < 256);

  for (int t = tid; t < 625; t += 128){
    int r = t / 25, la = t - r*25;
    float2 w = d_W[256*r*la];
    shWL[t] = make_float2(w.x, -w.y);
  }
  if (tid < 25){ float2 w = d_W25[tid]; shW25c[tid] = make_float2(w.x, -w.y); }
  __syncthreads();

  float2 u[25];
  if (act){
    const float2* src = d_work8 + (size_t)bs8*LTOT + (size_t)(rowok ? n1 : 0)*625;
    float2 v[25];
    #pragma unroll
    for (int r=0;r<25;r++) v[r] = rowok ? src[lane + 25*r] : make_float2(0.f,0.f);
    dft25i_sh(v, shW25c);
    #pragma unroll
    for (int r=0;r<25;r++) buf[row][lane*26 + r] = v[r];
  }
  __syncthreads();
  if (act){
    #pragma unroll
    for (int r=0;r<25;r++)
      u[r] = cmulf(buf[row][r*26 + lane], shWL[r*25 + lane]);
    dft25i_sh(u, shW25c);            // y_w + i*y_o at n2 = lane + 25r  (x L)
  }
  __syncthreads();
  float* eR = (float*)&buf[0][0];
  float* eI = eR + IROWS*625;
  const float invL = 1.0f/160000.0f;
  if (act){
    #pragma unroll
    for (int r=0;r<25;r++){
      int n2 = lane + 25*r;
      float yr = u[r].x * invL;
      float yi = u[r].y * invL;
      eR[row*625 + n2] = yr*yr;
      eI[row*625 + n2] = yi*yi;
    }
  }
  __syncthreads();
  for (int t = tid; t < IROWS*156; t += 128){
    int rr = t / 156, jb = t - rr*156;
    const float* e0 = eR + rr*625 + 4*jb;
    const float* e1 = eI + rr*625 + 4*jb;
    Psh[0][rr][jb] = (e0[0] + e0[1]) + (e0[2] + e0[3]);
    Psh[1][rr][jb] = (e1[0] + e1[1]) + (e1[2] + e1[3]);
  }
  __syncthreads();
  int bs1 = b*16 + s;        // watermarked
  int bs2 = b*16 + s + 8;    // original
  for (int t = tid; t < 2*156; t += 128){
    int half = t / 156, jb = t - half*156;
    float sum = ((Psh[half][0][jb] + Psh[half][1][jb]) +
                 (Psh[half][2][jb] + Psh[half][3][jb])) + Psh[half][4][jb];
    int bsx = half ? bs2 : bs1;
    d_P[((size_t)bsx*NBLK + jb)*NG2 + g] = sum;
  }
}

__global__ void k_red_all(){
  int idx = blockIdx.x*blockDim.x + threadIdx.x;
  if (idx < NBS*NBLK){
    const float* p = d_P + (size_t)idx*NG2;
    float sum = 0.f;
    #pragma unroll 4
    for (int i=0;i<NG2;i++) sum += p[i];
    d_blk[idx] = sum;
  }
}

__global__ void k_diff_all(){
  int t = blockIdx.x*blockDim.x + threadIdx.x;
  if (t < NDIFF){
    int s = t / (8*NCH);
    int rem = t - s*(8*NCH);
    int b = rem / NCH, jb = rem - b*NCH;
    float ew = d_blk[(b*16+s)*NBLK + jb]   + d_blk[(b*16+s)*NBLK + jb + 1];
    float eo = d_blk[(b*16+s+8)*NBLK + jb] + d_blk[(b*16+s+8)*NBLK + jb + 1];
    float lw = 10.f*log10f(ew*(1.f/2048.f) + 1e-12f);
    float lo = 10.f*log10f(eo*(1.f/2048.f) + 1e-12f);
    d_diff[t] = lw - lo;
  }
}

__global__ void __launch_bounds__(1024) k_final(float* __restrict__ out){
  __shared__ float smax[1024];
  __shared__ float ssum[1024];
  __shared__ float swt[1024];
  int tid = threadIdx.x;
  float m = -1e30f;
  for (int i = tid; i < NDIFF; i += 1024) m = fmaxf(m, d_diff[i]);
  smax[tid] = m; __syncthreads();
  for (int st = 512; st > 0; st >>= 1){
    if (tid < st) smax[tid] = fmaxf(smax[tid], smax[tid+st]);
    __syncthreads();
  }
  float mx = smax[0];
  float se = 0.f, sw = 0.f;
  for (int i = tid; i < NDIFF; i += 1024){
    float d = d_diff[i];
    float e = expf(d - mx);
    se += e;
    sw = fmaf(e, d, sw);
  }
  ssum[tid] = se; swt[tid] = sw; __syncthreads();
  for (int st = 512; st > 0; st >>= 1){
    if (tid < st){ ssum[tid] += ssum[tid+st]; swt[tid] += swt[tid+st]; }
    __syncthreads();
  }
  if (tid == 0) out[0] = swt[0] / ssum[0];
}

extern "C" void kernel_launch(void* const* d_in, const int* in_sizes, int n_in,
                              void* d_out, int out_size){
  const float* xw = (const float*)d_in[0];
  const float* xo = (const float*)d_in[1];
  float* out = (float*)d_out;

  k_genW<<<(LTOT+255)/256, 256>>>();
  k_fwd1<<<dim3(64,8), 512>>>(xw, xo);
  k_fwd2<<<1250, 256>>>();
  k_inv1_all<<<dim3(79,8,4), 128>>>();     // 79*8 = 632 >= 625 k2 rows; 4 band-pairs
  k_inv2_all<<<dim3(NG2,NPIPE), 128>>>();  // 52*5 = 260 >= 256 n1 rows
  k_red_all<<<(NBS*NBLK+255)/256, 256>>>();
  k_diff_all<<<(NDIFF+255)/256, 256>>>();
  k_final<<<1, 1024>>>(out);
}